// round 4
// baseline (speedup 1.0000x reference)
#include <cuda_runtime.h>
#include <math.h>

#define BATCH 16
#define HW 256
#define NT (BATCH*HW)   // 4096 total columns

// ---------------- scratch (no allocations allowed) ----------------
__device__ float g_h[BATCH*256*HW];      // conv_in output
__device__ float g_lnp[BATCH*128*HW];    // layernorm out (p)
__device__ float g_lnn[BATCH*128*HW];    // layernorm out (n)
__device__ float g_zp[BATCH*1024*HW];    // z_p (post-silu)
__device__ float g_zn[BATCH*1024*HW];    // z_n
__device__ float g_zqp[BATCH*1024*HW];   // zq_p channel layout
__device__ float g_zqn[BATCH*1024*HW];   // zq_n channel layout
__device__ float g_hcat[BATCH*256*HW];   // concat(hout_p, hout_n)
__device__ float g_cnorm[1024];
__device__ float g_loss_part[1024];      // 512 per branch
__device__ float g_lnstat[2][BATCH][8][2]; // partial (sum, sumsq)

__device__ __forceinline__ float silu_f(float v){ return v / (1.f + expf(-v)); }

// ---------------- packed fp32x2 helpers (each lane exact IEEE fp32) --------
typedef unsigned long long u64;
__device__ __forceinline__ u64 pack2(float a, float b){
  u64 r; asm("mov.b64 %0, {%1,%2};" : "=l"(r) : "f"(a), "f"(b)); return r;
}
__device__ __forceinline__ u64 fma2(u64 a, u64 b, u64 c){
  u64 d; asm("fma.rn.f32x2 %0, %1, %2, %3;" : "=l"(d) : "l"(a), "l"(b), "l"(c)); return d;
}
__device__ __forceinline__ void unpack2(u64 v, float& lo, float& hi){
  asm("mov.b64 {%0,%1}, %2;" : "=f"(lo), "=f"(hi) : "l"(v));
}

// ---------------- codebook norms (sequential fp32 chain) ----------------
__global__ void cnorm_kernel(const float* __restrict__ cb){
  int j = blockIdx.x*blockDim.x + threadIdx.x;
  if (j < 1024){
    float s = 0.f;
    #pragma unroll
    for (int e=0;e<32;e++){ float v = cb[j*32+e]; s = fmaf(v,v,s); }
    g_cnorm[j] = s;
  }
}

// ---------------- 1x1-conv GEMM, BM=128 BN=64 BK=16, f32x2 packed ----------
// grid: (NT/64, M/128, nsets) ; set z selects (W,bias,X,Y,oc_off).
// Per-output-element accumulation is strictly sequential over k (same order
// as rounds 1-3, preserving z bits feeding the VQ argmin).
template<bool SILU_IN, bool SILU_OUT>
__global__ void __launch_bounds__(256)
gemm_kernel(const float* __restrict__ W0, const float* __restrict__ W1,
            const float* __restrict__ bias0, const float* __restrict__ bias1,
            const float* __restrict__ X0, const float* __restrict__ X1,
            float* __restrict__ Y0, float* __restrict__ Y1,
            int Kd, int CinTot, int OCtot, int oc_off0, int oc_off1)
{
  const float* W    = blockIdx.z ? W1 : W0;
  const float* bias = blockIdx.z ? bias1 : bias0;
  const float* X    = blockIdx.z ? X1 : X0;
  float*       Y    = blockIdx.z ? Y1 : Y0;
  const int oc_off  = blockIdx.z ? oc_off1 : oc_off0;

  __shared__ __align__(16) float As[16][128];
  __shared__ __align__(16) float Bs[16][64];
  const int tid = threadIdx.x;
  const int tx = tid & 15, ty = tid >> 4;
  const int j0 = blockIdx.x * 64;
  const int m0 = blockIdx.y * 128;
  const int b  = j0 >> 8;
  const int p0 = j0 & 255;

  u64 acc2[4][4];
  #pragma unroll
  for (int i=0;i<4;i++)
    #pragma unroll
    for (int j=0;j<4;j++) acc2[i][j] = 0ull;   // bit pattern = {0.f,0.f}

  for (int k0=0;k0<Kd;k0+=16){
    #pragma unroll
    for (int i=0;i<8;i++){
      int e = tid + i*256;            // 2048 = 128 m x 16 k
      int m = e >> 4, k = e & 15;
      As[k][m] = W[(m0+m)*Kd + k0 + k];
    }
    #pragma unroll
    for (int i=0;i<4;i++){
      int e = tid + i*256;            // 1024 = 16 k x 64 j
      int k = e >> 6, j = e & 63;
      float v = X[((b*CinTot) + k0 + k)*HW + p0 + j];
      if (SILU_IN) v = silu_f(v);
      Bs[k][j] = v;
    }
    __syncthreads();
    #pragma unroll
    for (int kk=0;kk<16;kk++){
      ulonglong2 aA = *reinterpret_cast<const ulonglong2*>(&As[kk][ty*8]);
      ulonglong2 aB = *reinterpret_cast<const ulonglong2*>(&As[kk][ty*8+4]);
      float4 bv = *reinterpret_cast<const float4*>(&Bs[kk][tx*4]);
      u64 b0 = pack2(bv.x, bv.x), b1 = pack2(bv.y, bv.y);
      u64 b2 = pack2(bv.z, bv.z), b3 = pack2(bv.w, bv.w);
      acc2[0][0] = fma2(aA.x, b0, acc2[0][0]);
      acc2[0][1] = fma2(aA.x, b1, acc2[0][1]);
      acc2[0][2] = fma2(aA.x, b2, acc2[0][2]);
      acc2[0][3] = fma2(aA.x, b3, acc2[0][3]);
      acc2[1][0] = fma2(aA.y, b0, acc2[1][0]);
      acc2[1][1] = fma2(aA.y, b1, acc2[1][1]);
      acc2[1][2] = fma2(aA.y, b2, acc2[1][2]);
      acc2[1][3] = fma2(aA.y, b3, acc2[1][3]);
      acc2[2][0] = fma2(aB.x, b0, acc2[2][0]);
      acc2[2][1] = fma2(aB.x, b1, acc2[2][1]);
      acc2[2][2] = fma2(aB.x, b2, acc2[2][2]);
      acc2[2][3] = fma2(aB.x, b3, acc2[2][3]);
      acc2[3][0] = fma2(aB.y, b0, acc2[3][0]);
      acc2[3][1] = fma2(aB.y, b1, acc2[3][1]);
      acc2[3][2] = fma2(aB.y, b2, acc2[3][2]);
      acc2[3][3] = fma2(aB.y, b3, acc2[3][3]);
    }
    __syncthreads();
  }

  #pragma unroll
  for (int i=0;i<4;i++){
    int r0 = m0 + ty*8 + 2*i;
    float bb0 = bias[r0], bb1 = bias[r0+1];
    float lo[4], hi[4];
    #pragma unroll
    for (int j=0;j<4;j++) unpack2(acc2[i][j], lo[j], hi[j]);
    float4 o0, o1;
    o0.x = lo[0]+bb0; o0.y = lo[1]+bb0; o0.z = lo[2]+bb0; o0.w = lo[3]+bb0;
    o1.x = hi[0]+bb1; o1.y = hi[1]+bb1; o1.z = hi[2]+bb1; o1.w = hi[3]+bb1;
    if (SILU_OUT){
      o0.x = silu_f(o0.x); o0.y = silu_f(o0.y); o0.z = silu_f(o0.z); o0.w = silu_f(o0.w);
      o1.x = silu_f(o1.x); o1.y = silu_f(o1.y); o1.z = silu_f(o1.z); o1.w = silu_f(o1.w);
    }
    *reinterpret_cast<float4*>(&Y[((b*OCtot) + oc_off + r0  )*HW + p0 + tx*4]) = o0;
    *reinterpret_cast<float4*>(&Y[((b*OCtot) + oc_off + r0+1)*HW + p0 + tx*4]) = o1;
  }
}

// ---------------- layernorm: stats then apply, both branches via grid.z ----
__global__ void ln_stats_kernel(const float* __restrict__ H){
  const int c  = blockIdx.x;       // chunk 0..7
  const int b  = blockIdx.y;       // sample
  const int br = blockIdx.z;       // 0 = p (ch 0..127), 1 = n (ch 128..255)
  const float* base = H + (b*256 + br*128)*HW + c*4096;
  float s = 0.f, sq = 0.f;
  for (int i=threadIdx.x; i<4096; i+=256){
    float v = silu_f(base[i]);
    s += v; sq = fmaf(v, v, sq);
  }
  __shared__ float rs[8], rq[8];
  #pragma unroll
  for (int o=16;o>0;o>>=1){
    s  += __shfl_down_sync(0xffffffffu, s,  o);
    sq += __shfl_down_sync(0xffffffffu, sq, o);
  }
  int wid = threadIdx.x >> 5, lid = threadIdx.x & 31;
  if (lid == 0){ rs[wid] = s; rq[wid] = sq; }
  __syncthreads();
  if (threadIdx.x == 0){
    float ts = 0.f, tq = 0.f;
    #pragma unroll
    for (int i=0;i<8;i++){ ts += rs[i]; tq += rq[i]; }
    g_lnstat[br][b][c][0] = ts;
    g_lnstat[br][b][c][1] = tq;
  }
}

__global__ void ln_apply_kernel(const float* __restrict__ H,
                                const float* __restrict__ wp, const float* __restrict__ bp,
                                const float* __restrict__ wn, const float* __restrict__ bn,
                                float* __restrict__ outp, float* __restrict__ outn)
{
  const int c  = blockIdx.x;
  const int b  = blockIdx.y;
  const int br = blockIdx.z;
  float s = 0.f, sq = 0.f;
  #pragma unroll
  for (int i=0;i<8;i++){ s += g_lnstat[br][b][i][0]; sq += g_lnstat[br][b][i][1]; }
  float mu   = s * (1.f/32768.f);
  float var  = sq * (1.f/32768.f) - mu*mu;
  float rstd = rsqrtf(var + 1e-5f);
  const float* base = H + (b*256 + br*128)*HW + c*4096;
  const float* w  = (br ? wn : wp) + c*4096;
  const float* bb = (br ? bn : bp) + c*4096;
  float* ob = (br ? outn : outp) + b*32768 + c*4096;
  for (int i=threadIdx.x; i<4096; i+=256){
    float v = silu_f(base[i]);
    ob[i] = (v - mu) * rstd * w[i] + bb[i];
  }
}

// ---------------- fused VQ with f32x2-packed candidate pairs ----------------
// channel index c = e*(LV*KP) + l*KP + kp ; flat vector n = kp*256 + p
// Per-candidate dot is a strictly sequential fp32 fma chain over e = 0..31
// (one f32x2 lane per candidate), then score = (zz - 2*zc) + cc — identical
// rounding structure to round 3 (bit-identical scores).
template<int KP, int LV, bool WRITE_OUT>
__global__ void __launch_bounds__(256)
quantize_kernel(const float* __restrict__ Z, const float* __restrict__ cb,
                float* __restrict__ zq_out, float* __restrict__ zq_chan,
                float* __restrict__ loss_slot)
{
  const int bx = blockIdx.x;
  const int l  = bx % LV;
  const int kp = (bx / LV) % KP;
  const int b  = bx / (LV*KP);
  const int p  = threadIdx.x;

  u64 z2[32];
  float zz = 0.f;
  #pragma unroll
  for (int e=0;e<32;e++){
    float v = Z[((b*1024 + e*(LV*KP) + l*KP + kp)*HW) + p];
    zz = fmaf(v, v, zz);
    z2[e] = pack2(v, v);
  }

  // pair-interleaved codebook tile: sP[pp*64 + 2*e + s] = cb[(ch+2*pp+s)*32+e]
  __shared__ __align__(16) float sP[8192];
  __shared__ float sN[128];
  float best = 3.4e38f; int bestj = 0;

  for (int ch=0; ch<1024; ch+=128){
    #pragma unroll
    for (int it=0; it<32; it++){
      int idx = threadIdx.x + it*256;
      int pp = idx >> 6, r = idx & 63;
      sP[idx] = cb[(ch + 2*pp + (r & 1))*32 + (r >> 1)];
    }
    if (threadIdx.x < 128) sN[threadIdx.x] = g_cnorm[ch + threadIdx.x];
    __syncthreads();

    for (int pp=0; pp<64; pp+=2){
      const ulonglong2* q0 = reinterpret_cast<const ulonglong2*>(&sP[(pp  )*64]);
      const ulonglong2* q1 = reinterpret_cast<const ulonglong2*>(&sP[(pp+1)*64]);
      u64 A0 = 0ull, A1 = 0ull;
      #pragma unroll
      for (int q=0;q<16;q++){
        ulonglong2 P0 = q0[q];
        ulonglong2 P1 = q1[q];
        A0 = fma2(z2[2*q  ], P0.x, A0);
        A1 = fma2(z2[2*q  ], P1.x, A1);
        A0 = fma2(z2[2*q+1], P0.y, A0);
        A1 = fma2(z2[2*q+1], P1.y, A1);
      }
      float a0,a1,a2,a3;
      unpack2(A0, a0, a1);
      unpack2(A1, a2, a3);
      float s0 = (zz - 2.f*a0) + sN[2*pp+0];
      float s1 = (zz - 2.f*a1) + sN[2*pp+1];
      float s2 = (zz - 2.f*a2) + sN[2*pp+2];
      float s3 = (zz - 2.f*a3) + sN[2*pp+3];
      if (s0 < best){ best = s0; bestj = ch + 2*pp + 0; }
      if (s1 < best){ best = s1; bestj = ch + 2*pp + 1; }
      if (s2 < best){ best = s2; bestj = ch + 2*pp + 2; }
      if (s3 < best){ best = s3; bestj = ch + 2*pp + 3; }
    }
    __syncthreads();
  }

  // loss contribution (deterministic per-block sum)
  float s = best;
  #pragma unroll
  for (int o=16;o>0;o>>=1) s += __shfl_down_sync(0xffffffffu, s, o);
  __shared__ float red[8];
  if ((threadIdx.x & 31) == 0) red[threadIdx.x >> 5] = s;
  __syncthreads();
  if (threadIdx.x == 0){
    float t = 0.f;
    #pragma unroll
    for (int i=0;i<8;i++) t += red[i];
    loss_slot[blockIdx.x] = t;
  }

  const float4* cbest = reinterpret_cast<const float4*>(cb + bestj*32);
  #pragma unroll
  for (int q=0;q<8;q++){
    float4 v4 = cbest[q];
    float vv[4] = {v4.x, v4.y, v4.z, v4.w};
    #pragma unroll
    for (int r=0;r<4;r++){
      int e = q*4 + r;
      zq_chan[(b*1024 + e*(LV*KP) + l*KP + kp)*HW + p] = vv[r];
      if (WRITE_OUT)
        zq_out[(((b*32 + e)*(KP*HW)) + kp*HW + p)*LV + l] = vv[r];
    }
  }
}

// ---------------- deterministic loss finalize ----------------
__global__ void loss_final_kernel(float* __restrict__ out_loss){
  __shared__ float red[256];
  float s = 0.f;
  for (int i=threadIdx.x; i<1024; i+=256) s += g_loss_part[i];
  red[threadIdx.x] = s;
  __syncthreads();
  for (int o=128;o>0;o>>=1){
    if (threadIdx.x < o) red[threadIdx.x] += red[threadIdx.x + o];
    __syncthreads();
  }
  if (threadIdx.x == 0)
    *out_loss = 1.25f * red[0] / 4194304.f;
}

// ---------------- launch ----------------
extern "C" void kernel_launch(void* const* d_in, const int* in_sizes, int n_in,
                              void* d_out, int out_size)
{
  const float* x          = (const float*)d_in[0];
  const float* conv_in_w  = (const float*)d_in[1];
  const float* conv_in_b  = (const float*)d_in[2];
  const float* ln_p_w     = (const float*)d_in[3];
  const float* ln_p_b     = (const float*)d_in[4];
  const float* wp_in      = (const float*)d_in[5];
  const float* bp_in      = (const float*)d_in[6];
  const float* wp_out     = (const float*)d_in[7];
  const float* bp_out     = (const float*)d_in[8];
  const float* ln_n_w     = (const float*)d_in[9];
  const float* ln_n_b     = (const float*)d_in[10];
  const float* wn_in      = (const float*)d_in[11];
  const float* bn_in      = (const float*)d_in[12];
  const float* wn_out     = (const float*)d_in[13];
  const float* bn_out     = (const float*)d_in[14];
  const float* codebook   = (const float*)d_in[15];
  const float* conv_out_w = (const float*)d_in[16];
  const float* conv_out_b = (const float*)d_in[17];

  float* out      = (float*)d_out;               // [16,256,16,16]
  float* out_loss = out + 1048576;               // scalar
  float* out_zq   = out + 1048577;               // [16,32,2048,4]

  float *hbuf,*lnp,*lnn,*zp,*zn,*zqp,*zqn,*hcat,*lpart;
  cudaGetSymbolAddress((void**)&hbuf,  g_h);
  cudaGetSymbolAddress((void**)&lnp,   g_lnp);
  cudaGetSymbolAddress((void**)&lnn,   g_lnn);
  cudaGetSymbolAddress((void**)&zp,    g_zp);
  cudaGetSymbolAddress((void**)&zn,    g_zn);
  cudaGetSymbolAddress((void**)&zqp,   g_zqp);
  cudaGetSymbolAddress((void**)&zqn,   g_zqn);
  cudaGetSymbolAddress((void**)&hcat,  g_hcat);
  cudaGetSymbolAddress((void**)&lpart, g_loss_part);

  cnorm_kernel<<<4, 256>>>(codebook);

  // h = conv_in(silu(x))   M=256 -> grid y=2
  gemm_kernel<true,false><<<dim3(64, 2, 1), 256>>>(
      conv_in_w, conv_in_w, conv_in_b, conv_in_b, x, x, hbuf, hbuf,
      256, 256, 256, 0, 0);

  // layernorms (both branches)
  ln_stats_kernel<<<dim3(8, BATCH, 2), 256>>>(hbuf);
  ln_apply_kernel<<<dim3(8, BATCH, 2), 256>>>(hbuf, ln_p_w, ln_p_b, ln_n_w, ln_n_b, lnp, lnn);

  // z = silu(W_in @ ln + b)   M=1024 -> grid y=8, z selects branch
  gemm_kernel<false,true><<<dim3(64, 8, 2), 256>>>(
      wp_in, wn_in, bp_in, bn_in, lnp, lnn, zp, zn,
      128, 128, 1024, 0, 0);

  // VQ
  quantize_kernel<8,4,true><<<BATCH*8*4, 256>>>(zp, codebook, out_zq, zqp, lpart);
  quantize_kernel<32,1,false><<<BATCH*32*1, 256>>>(zn, codebook, nullptr, zqn, lpart + 512);

  // hout = silu(W_out @ zq + b) into concat buffer   M=128 -> grid y=1, z branch
  gemm_kernel<false,true><<<dim3(64, 1, 2), 256>>>(
      wp_out, wn_out, bp_out, bn_out, zqp, zqn, hcat, hcat,
      1024, 1024, 256, 0, 128);

  // out = conv_out(silu(h_cat))
  gemm_kernel<true,false><<<dim3(64, 2, 1), 256>>>(
      conv_out_w, conv_out_w, conv_out_b, conv_out_b, hcat, hcat, out, out,
      256, 256, 256, 0, 0);

  loss_final_kernel<<<1, 256>>>(out_loss);
}

// round 5
// speedup vs baseline: 1.7132x; 1.7132x over previous
#include <cuda_runtime.h>
#include <math.h>

#define BATCH 16
#define HW 256
#define NT (BATCH*HW)   // 4096 total columns

// ---------------- scratch (no allocations allowed) ----------------
__device__ float g_h[BATCH*256*HW];      // conv_in output
__device__ float g_lnp[BATCH*128*HW];    // layernorm out (p)
__device__ float g_lnn[BATCH*128*HW];    // layernorm out (n)
__device__ float g_zp[BATCH*1024*HW];    // z_p (post-silu)
__device__ float g_zn[BATCH*1024*HW];    // z_n
__device__ float g_zqp[BATCH*1024*HW];   // zq_p channel layout
__device__ float g_zqn[BATCH*1024*HW];   // zq_n channel layout
__device__ float g_hcat[BATCH*256*HW];   // concat(hout_p, hout_n)
__device__ float g_cnorm[1024];
__device__ float g_loss_part[1024];      // 512 per branch
__device__ float g_lnstat[2][BATCH][8][2]; // partial (sum, sumsq)

__device__ __forceinline__ float silu_f(float v){ return v / (1.f + expf(-v)); }

// ---------------- codebook norms (sequential fp32 chain) ----------------
__global__ void cnorm_kernel(const float* __restrict__ cb){
  int j = blockIdx.x*blockDim.x + threadIdx.x;
  if (j < 1024){
    float s = 0.f;
    #pragma unroll
    for (int e=0;e<32;e++){ float v = cb[j*32+e]; s = fmaf(v,v,s); }
    g_cnorm[j] = s;
  }
}

// ---------------- 1x1-conv GEMM, BM=BN=64 BK=16, scalar FFMA (R3) ----------
// grid: (NT/64, M/64, nsets); z selects parameter set (sibling-branch merge).
// Per-output accumulation strictly sequential over k (bit-identical to R3).
template<bool SILU_IN, bool SILU_OUT>
__global__ void __launch_bounds__(256)
gemm_kernel(const float* __restrict__ W0, const float* __restrict__ W1,
            const float* __restrict__ bias0, const float* __restrict__ bias1,
            const float* __restrict__ X0, const float* __restrict__ X1,
            float* __restrict__ Y0, float* __restrict__ Y1,
            int Kd, int CinTot, int OCtot, int oc_off0, int oc_off1)
{
  const float* W    = blockIdx.z ? W1 : W0;
  const float* bias = blockIdx.z ? bias1 : bias0;
  const float* X    = blockIdx.z ? X1 : X0;
  float*       Y    = blockIdx.z ? Y1 : Y0;
  const int oc_off  = blockIdx.z ? oc_off1 : oc_off0;

  __shared__ __align__(16) float As[16][64];
  __shared__ __align__(16) float Bs[16][64];
  const int tid = threadIdx.x;
  const int tx = tid & 15, ty = tid >> 4;
  const int j0 = blockIdx.x * 64;
  const int m0 = blockIdx.y * 64;
  const int b  = j0 >> 8;
  const int p0 = j0 & 255;

  float acc[4][4];
  #pragma unroll
  for (int i=0;i<4;i++)
    #pragma unroll
    for (int j=0;j<4;j++) acc[i][j] = 0.f;

  for (int k0=0;k0<Kd;k0+=16){
    #pragma unroll
    for (int i=0;i<4;i++){
      int e = tid + i*256;
      int m = e >> 4, k = e & 15;
      As[k][m] = W[(m0+m)*Kd + k0 + k];
    }
    #pragma unroll
    for (int i=0;i<4;i++){
      int e = tid + i*256;
      int k = e >> 6, j = e & 63;
      float v = X[((b*CinTot) + k0 + k)*HW + p0 + j];
      if (SILU_IN) v = silu_f(v);
      Bs[k][j] = v;
    }
    __syncthreads();
    #pragma unroll
    for (int kk=0;kk<16;kk++){
      float4 a  = *reinterpret_cast<const float4*>(&As[kk][ty*4]);
      float4 bv = *reinterpret_cast<const float4*>(&Bs[kk][tx*4]);
      float av[4] = {a.x,a.y,a.z,a.w};
      float bb[4] = {bv.x,bv.y,bv.z,bv.w};
      #pragma unroll
      for (int i=0;i<4;i++)
        #pragma unroll
        for (int j=0;j<4;j++)
          acc[i][j] = fmaf(av[i], bb[j], acc[i][j]);
    }
    __syncthreads();
  }

  #pragma unroll
  for (int i=0;i<4;i++){
    int m = m0 + ty*4 + i;
    float bb = bias[m];
    float4 o;
    o.x = acc[i][0] + bb; o.y = acc[i][1] + bb;
    o.z = acc[i][2] + bb; o.w = acc[i][3] + bb;
    if (SILU_OUT){
      o.x = silu_f(o.x); o.y = silu_f(o.y); o.z = silu_f(o.z); o.w = silu_f(o.w);
    }
    *reinterpret_cast<float4*>(&Y[((b*OCtot) + oc_off + m)*HW + p0 + tx*4]) = o;
  }
}

// ---------------- layernorm: stats then apply, both branches via grid.z ----
__global__ void ln_stats_kernel(const float* __restrict__ H){
  const int c  = blockIdx.x;       // chunk 0..7
  const int b  = blockIdx.y;       // sample
  const int br = blockIdx.z;       // 0 = p (ch 0..127), 1 = n (ch 128..255)
  const float* base = H + (b*256 + br*128)*HW + c*4096;
  float s = 0.f, sq = 0.f;
  for (int i=threadIdx.x; i<4096; i+=256){
    float v = silu_f(base[i]);
    s += v; sq = fmaf(v, v, sq);
  }
  __shared__ float rs[8], rq[8];
  #pragma unroll
  for (int o=16;o>0;o>>=1){
    s  += __shfl_down_sync(0xffffffffu, s,  o);
    sq += __shfl_down_sync(0xffffffffu, sq, o);
  }
  int wid = threadIdx.x >> 5, lid = threadIdx.x & 31;
  if (lid == 0){ rs[wid] = s; rq[wid] = sq; }
  __syncthreads();
  if (threadIdx.x == 0){
    float ts = 0.f, tq = 0.f;
    #pragma unroll
    for (int i=0;i<8;i++){ ts += rs[i]; tq += rq[i]; }
    g_lnstat[br][b][c][0] = ts;
    g_lnstat[br][b][c][1] = tq;
  }
}

__global__ void ln_apply_kernel(const float* __restrict__ H,
                                const float* __restrict__ wp, const float* __restrict__ bp,
                                const float* __restrict__ wn, const float* __restrict__ bn,
                                float* __restrict__ outp, float* __restrict__ outn)
{
  const int c  = blockIdx.x;
  const int b  = blockIdx.y;
  const int br = blockIdx.z;
  float s = 0.f, sq = 0.f;
  #pragma unroll
  for (int i=0;i<8;i++){ s += g_lnstat[br][b][i][0]; sq += g_lnstat[br][b][i][1]; }
  float mu   = s * (1.f/32768.f);
  float var  = sq * (1.f/32768.f) - mu*mu;
  float rstd = rsqrtf(var + 1e-5f);
  const float* base = H + (b*256 + br*128)*HW + c*4096;
  const float* w  = (br ? wn : wp) + c*4096;
  const float* bb = (br ? bn : bp) + c*4096;
  float* ob = (br ? outn : outp) + b*32768 + c*4096;
  for (int i=threadIdx.x; i<4096; i+=256){
    float v = silu_f(base[i]);
    ob[i] = (v - mu) * rstd * w[i] + bb[i];
  }
}

// ---------------- fused VQ (R3 scalar body as device function) -------------
// channel c = e*(LV*KP) + l*KP + kp ; flat vector n = kp*256 + p
// Per-candidate dot: strictly sequential fp32 fma chain over e = 0..31
// (Eigen gebp order); score = (zz - 2*zc) + cc. Bit-identical to round 3.
template<int KP, int LV, bool WRITE_OUT>
__device__ __forceinline__ void quant_body(
    int bx, const float* __restrict__ Z, const float* __restrict__ cb,
    float* __restrict__ zq_out, float* __restrict__ zq_chan,
    float* __restrict__ loss_slot, float* sC, float* sN)
{
  const int l  = bx % LV;
  const int kp = (bx / LV) % KP;
  const int b  = bx / (LV*KP);
  const int p  = threadIdx.x;

  float z[32];
  float zz = 0.f;
  #pragma unroll
  for (int e=0;e<32;e++){
    float v = Z[((b*1024 + e*(LV*KP) + l*KP + kp)*HW) + p];
    z[e] = v; zz = fmaf(v, v, zz);
  }

  float best = 3.4e38f; int bestj = 0;

  for (int ch=0; ch<1024; ch+=128){
    for (int i=threadIdx.x; i<4096; i+=256) sC[i] = cb[ch*32 + i];
    if (threadIdx.x < 128) sN[threadIdx.x] = g_cnorm[ch + threadIdx.x];
    __syncthreads();
    for (int jj=0;jj<128;jj+=4){
      const float4* c0 = reinterpret_cast<const float4*>(&sC[(jj+0)*32]);
      const float4* c1 = reinterpret_cast<const float4*>(&sC[(jj+1)*32]);
      const float4* c2 = reinterpret_cast<const float4*>(&sC[(jj+2)*32]);
      const float4* c3 = reinterpret_cast<const float4*>(&sC[(jj+3)*32]);
      float a0=0.f, a1=0.f, a2=0.f, a3=0.f;
      #pragma unroll
      for (int q=0;q<8;q++){
        float4 v0 = c0[q], v1 = c1[q], v2 = c2[q], v3 = c3[q];
        float vv0[4] = {v0.x,v0.y,v0.z,v0.w};
        float vv1[4] = {v1.x,v1.y,v1.z,v1.w};
        float vv2[4] = {v2.x,v2.y,v2.z,v2.w};
        float vv3[4] = {v3.x,v3.y,v3.z,v3.w};
        #pragma unroll
        for (int r=0;r<4;r++){
          float ze = z[4*q+r];
          a0 = fmaf(ze, vv0[r], a0);
          a1 = fmaf(ze, vv1[r], a1);
          a2 = fmaf(ze, vv2[r], a2);
          a3 = fmaf(ze, vv3[r], a3);
        }
      }
      float s0 = (zz - 2.f*a0) + sN[jj+0];
      float s1 = (zz - 2.f*a1) + sN[jj+1];
      float s2 = (zz - 2.f*a2) + sN[jj+2];
      float s3 = (zz - 2.f*a3) + sN[jj+3];
      if (s0 < best){ best = s0; bestj = ch + jj + 0; }
      if (s1 < best){ best = s1; bestj = ch + jj + 1; }
      if (s2 < best){ best = s2; bestj = ch + jj + 2; }
      if (s3 < best){ best = s3; bestj = ch + jj + 3; }
    }
    __syncthreads();
  }

  // loss contribution (deterministic per-block sum)
  float s = best;
  #pragma unroll
  for (int o=16;o>0;o>>=1) s += __shfl_down_sync(0xffffffffu, s, o);
  __shared__ float red[8];
  if ((threadIdx.x & 31) == 0) red[threadIdx.x >> 5] = s;
  __syncthreads();
  if (threadIdx.x == 0){
    float t = 0.f;
    #pragma unroll
    for (int i=0;i<8;i++) t += red[i];
    loss_slot[bx] = t;
  }

  const float4* cbest = reinterpret_cast<const float4*>(cb + bestj*32);
  #pragma unroll
  for (int q=0;q<8;q++){
    float4 v4 = cbest[q];
    float vv[4] = {v4.x, v4.y, v4.z, v4.w};
    #pragma unroll
    for (int r=0;r<4;r++){
      int e = q*4 + r;
      zq_chan[(b*1024 + e*(LV*KP) + l*KP + kp)*HW + p] = vv[r];
      if (WRITE_OUT)
        zq_out[(((b*32 + e)*(KP*HW)) + kp*HW + p)*LV + l] = vv[r];
    }
  }
}

// one launch for both branches: blocks [0,512) = p, [512,1024) = n
__global__ void __launch_bounds__(256)
quantize_all_kernel(const float* __restrict__ Zp, const float* __restrict__ Zn,
                    const float* __restrict__ cb,
                    float* __restrict__ zq_out,
                    float* __restrict__ zqp_chan, float* __restrict__ zqn_chan,
                    float* __restrict__ loss_part)
{
  __shared__ __align__(16) float sC[128*32];
  __shared__ float sN[128];
  if (blockIdx.x < 512){
    quant_body<8,4,true >(blockIdx.x, Zp, cb, zq_out, zqp_chan, loss_part, sC, sN);
  } else {
    quant_body<32,1,false>(blockIdx.x - 512, Zn, cb, nullptr, zqn_chan, loss_part + 512, sC, sN);
  }
}

// ---------------- deterministic loss finalize ----------------
__global__ void loss_final_kernel(float* __restrict__ out_loss){
  __shared__ float red[256];
  float s = 0.f;
  for (int i=threadIdx.x; i<1024; i+=256) s += g_loss_part[i];
  red[threadIdx.x] = s;
  __syncthreads();
  for (int o=128;o>0;o>>=1){
    if (threadIdx.x < o) red[threadIdx.x] += red[threadIdx.x + o];
    __syncthreads();
  }
  if (threadIdx.x == 0)
    *out_loss = 1.25f * red[0] / 4194304.f;
}

// ---------------- launch ----------------
extern "C" void kernel_launch(void* const* d_in, const int* in_sizes, int n_in,
                              void* d_out, int out_size)
{
  const float* x          = (const float*)d_in[0];
  const float* conv_in_w  = (const float*)d_in[1];
  const float* conv_in_b  = (const float*)d_in[2];
  const float* ln_p_w     = (const float*)d_in[3];
  const float* ln_p_b     = (const float*)d_in[4];
  const float* wp_in      = (const float*)d_in[5];
  const float* bp_in      = (const float*)d_in[6];
  const float* wp_out     = (const float*)d_in[7];
  const float* bp_out     = (const float*)d_in[8];
  const float* ln_n_w     = (const float*)d_in[9];
  const float* ln_n_b     = (const float*)d_in[10];
  const float* wn_in      = (const float*)d_in[11];
  const float* bn_in      = (const float*)d_in[12];
  const float* wn_out     = (const float*)d_in[13];
  const float* bn_out     = (const float*)d_in[14];
  const float* codebook   = (const float*)d_in[15];
  const float* conv_out_w = (const float*)d_in[16];
  const float* conv_out_b = (const float*)d_in[17];

  float* out      = (float*)d_out;               // [16,256,16,16]
  float* out_loss = out + 1048576;               // scalar
  float* out_zq   = out + 1048577;               // [16,32,2048,4]

  float *hbuf,*lnp,*lnn,*zp,*zn,*zqp,*zqn,*hcat,*lpart;
  cudaGetSymbolAddress((void**)&hbuf,  g_h);
  cudaGetSymbolAddress((void**)&lnp,   g_lnp);
  cudaGetSymbolAddress((void**)&lnn,   g_lnn);
  cudaGetSymbolAddress((void**)&zp,    g_zp);
  cudaGetSymbolAddress((void**)&zn,    g_zn);
  cudaGetSymbolAddress((void**)&zqp,   g_zqp);
  cudaGetSymbolAddress((void**)&zqn,   g_zqn);
  cudaGetSymbolAddress((void**)&hcat,  g_hcat);
  cudaGetSymbolAddress((void**)&lpart, g_loss_part);

  cnorm_kernel<<<4, 256>>>(codebook);

  // h = conv_in(silu(x))   M=256 -> grid (64,4,1)
  gemm_kernel<true,false><<<dim3(64, 4, 1), 256>>>(
      conv_in_w, conv_in_w, conv_in_b, conv_in_b, x, x, hbuf, hbuf,
      256, 256, 256, 0, 0);

  // layernorms (both branches)
  ln_stats_kernel<<<dim3(8, BATCH, 2), 256>>>(hbuf);
  ln_apply_kernel<<<dim3(8, BATCH, 2), 256>>>(hbuf, ln_p_w, ln_p_b, ln_n_w, ln_n_b, lnp, lnn);

  // z = silu(W_in @ ln + b)   M=1024 -> grid (64,16,2)
  gemm_kernel<false,true><<<dim3(64, 16, 2), 256>>>(
      wp_in, wn_in, bp_in, bn_in, lnp, lnn, zp, zn,
      128, 128, 1024, 0, 0);

  // VQ, both branches in one launch
  quantize_all_kernel<<<1024, 256>>>(zp, zn, codebook, out_zq, zqp, zqn, lpart);

  // hout = silu(W_out @ zq + b) into concat buffer   M=128 -> grid (64,2,2)
  gemm_kernel<false,true><<<dim3(64, 2, 2), 256>>>(
      wp_out, wn_out, bp_out, bn_out, zqp, zqn, hcat, hcat,
      1024, 1024, 256, 0, 128);

  // out = conv_out(silu(h_cat))   M=256 -> grid (64,4,1)
  gemm_kernel<true,false><<<dim3(64, 4, 1), 256>>>(
      conv_out_w, conv_out_w, conv_out_b, conv_out_b, hcat, hcat, out, out,
      256, 256, 256, 0, 0);

  loss_final_kernel<<<1, 256>>>(out_loss);
}

// round 7
// speedup vs baseline: 1.8108x; 1.0569x over previous
#include <cuda_runtime.h>
#include <math.h>

#define BATCH 16
#define HW 256
#define NT (BATCH*HW)   // 4096 total columns

// ---------------- scratch (no allocations allowed) ----------------
__device__ float g_h[BATCH*256*HW];      // conv_in output
__device__ float g_lnp[BATCH*128*HW];    // layernorm out (p)
__device__ float g_lnn[BATCH*128*HW];    // layernorm out (n)
__device__ float g_zp[BATCH*1024*HW];    // z_p (post-silu)
__device__ float g_zn[BATCH*1024*HW];    // z_n
__device__ float g_zqp[BATCH*1024*HW];   // zq_p channel layout
__device__ float g_zqn[BATCH*1024*HW];   // zq_n channel layout
__device__ float g_hcat[BATCH*256*HW];   // concat(hout_p, hout_n)
__device__ float g_cnorm[1024];
__device__ float g_loss_part[1024];      // 512 per branch
__device__ float g_lnstat[2][BATCH][8][2]; // partial (sum, sumsq)

__device__ __forceinline__ float silu_f(float v){ return v / (1.f + expf(-v)); }

// ---------------- codebook norms (sequential fp32 chain) ----------------
__global__ void cnorm_kernel(const float* __restrict__ cb){
  int j = blockIdx.x*blockDim.x + threadIdx.x;
  if (j < 1024){
    float s = 0.f;
    #pragma unroll
    for (int e=0;e<32;e++){ float v = cb[j*32+e]; s = fmaf(v,v,s); }
    g_cnorm[j] = s;
  }
}

// ---------------- 1x1-conv GEMM, BM=128 BN=64 BK=16, scalar FFMA ----------
// 8x4 register tile per thread (256 threads). Per-output accumulation is
// strictly sequential over k in the same order as rounds 3/5 -> bit-identical.
// grid: (NT/64, M/128, nsets); z selects parameter set (sibling-branch merge).
template<bool SILU_IN, bool SILU_OUT>
__global__ void __launch_bounds__(256)
gemm_kernel(const float* __restrict__ W0, const float* __restrict__ W1,
            const float* __restrict__ bias0, const float* __restrict__ bias1,
            const float* __restrict__ X0, const float* __restrict__ X1,
            float* __restrict__ Y0, float* __restrict__ Y1,
            int Kd, int CinTot, int OCtot, int oc_off0, int oc_off1)
{
  const float* W    = blockIdx.z ? W1 : W0;
  const float* bias = blockIdx.z ? bias1 : bias0;
  const float* X    = blockIdx.z ? X1 : X0;
  float*       Y    = blockIdx.z ? Y1 : Y0;
  const int oc_off  = blockIdx.z ? oc_off1 : oc_off0;

  __shared__ __align__(16) float As[16][128];
  __shared__ __align__(16) float Bs[16][64];
  const int tid = threadIdx.x;
  const int tx = tid & 15, ty = tid >> 4;
  const int j0 = blockIdx.x * 64;
  const int m0 = blockIdx.y * 128;
  const int b  = j0 >> 8;
  const int p0 = j0 & 255;

  float acc[8][4];
  #pragma unroll
  for (int i=0;i<8;i++)
    #pragma unroll
    for (int j=0;j<4;j++) acc[i][j] = 0.f;

  for (int k0=0;k0<Kd;k0+=16){
    #pragma unroll
    for (int i=0;i<8;i++){
      int e = tid + i*256;            // 2048 = 128 m x 16 k
      int m = e >> 4, k = e & 15;
      As[k][m] = W[(m0+m)*Kd + k0 + k];
    }
    #pragma unroll
    for (int i=0;i<4;i++){
      int e = tid + i*256;            // 1024 = 16 k x 64 j
      int k = e >> 6, j = e & 63;
      float v = X[((b*CinTot) + k0 + k)*HW + p0 + j];
      if (SILU_IN) v = silu_f(v);
      Bs[k][j] = v;
    }
    __syncthreads();
    #pragma unroll
    for (int kk=0;kk<16;kk++){
      float4 a0 = *reinterpret_cast<const float4*>(&As[kk][ty*8]);
      float4 a1 = *reinterpret_cast<const float4*>(&As[kk][ty*8+4]);
      float4 bv = *reinterpret_cast<const float4*>(&Bs[kk][tx*4]);
      float av[8] = {a0.x,a0.y,a0.z,a0.w,a1.x,a1.y,a1.z,a1.w};
      float bb[4] = {bv.x,bv.y,bv.z,bv.w};
      #pragma unroll
      for (int i=0;i<8;i++)
        #pragma unroll
        for (int j=0;j<4;j++)
          acc[i][j] = fmaf(av[i], bb[j], acc[i][j]);
    }
    __syncthreads();
  }

  #pragma unroll
  for (int i=0;i<8;i++){
    int m = m0 + ty*8 + i;
    float bb = bias[m];
    float4 o;
    o.x = acc[i][0] + bb; o.y = acc[i][1] + bb;
    o.z = acc[i][2] + bb; o.w = acc[i][3] + bb;
    if (SILU_OUT){
      o.x = silu_f(o.x); o.y = silu_f(o.y); o.z = silu_f(o.z); o.w = silu_f(o.w);
    }
    *reinterpret_cast<float4*>(&Y[((b*OCtot) + oc_off + m)*HW + p0 + tx*4]) = o;
  }
}

// ---------------- layernorm: stats then apply, both branches via grid.z ----
__global__ void ln_stats_kernel(const float* __restrict__ H){
  const int c  = blockIdx.x;       // chunk 0..7
  const int b  = blockIdx.y;       // sample
  const int br = blockIdx.z;       // 0 = p (ch 0..127), 1 = n (ch 128..255)
  const float* base = H + (b*256 + br*128)*HW + c*4096;
  float s = 0.f, sq = 0.f;
  for (int i=threadIdx.x; i<4096; i+=256){
    float v = silu_f(base[i]);
    s += v; sq = fmaf(v, v, sq);
  }
  __shared__ float rs[8], rq[8];
  #pragma unroll
  for (int o=16;o>0;o>>=1){
    s  += __shfl_down_sync(0xffffffffu, s,  o);
    sq += __shfl_down_sync(0xffffffffu, sq, o);
  }
  int wid = threadIdx.x >> 5, lid = threadIdx.x & 31;
  if (lid == 0){ rs[wid] = s; rq[wid] = sq; }
  __syncthreads();
  if (threadIdx.x == 0){
    float ts = 0.f, tq = 0.f;
    #pragma unroll
    for (int i=0;i<8;i++){ ts += rs[i]; tq += rq[i]; }
    g_lnstat[br][b][c][0] = ts;
    g_lnstat[br][b][c][1] = tq;
  }
}

__global__ void ln_apply_kernel(const float* __restrict__ H,
                                const float* __restrict__ wp, const float* __restrict__ bp,
                                const float* __restrict__ wn, const float* __restrict__ bn,
                                float* __restrict__ outp, float* __restrict__ outn)
{
  const int c  = blockIdx.x;
  const int b  = blockIdx.y;
  const int br = blockIdx.z;
  float s = 0.f, sq = 0.f;
  #pragma unroll
  for (int i=0;i<8;i++){ s += g_lnstat[br][b][i][0]; sq += g_lnstat[br][b][i][1]; }
  float mu   = s * (1.f/32768.f);
  float var  = sq * (1.f/32768.f) - mu*mu;
  float rstd = rsqrtf(var + 1e-5f);
  const float* base = H + (b*256 + br*128)*HW + c*4096;
  const float* w  = (br ? wn : wp) + c*4096;
  const float* bb = (br ? bn : bp) + c*4096;
  float* ob = (br ? outn : outp) + b*32768 + c*4096;
  for (int i=threadIdx.x; i<4096; i+=256){
    float v = silu_f(base[i]);
    ob[i] = (v - mu) * rstd * w[i] + bb[i];
  }
}

// ---------------- fused VQ: TWO vector-groups per block --------------------
// channel c = e*(LV*KP) + l*KP + kp ; flat vector n = kp*256 + p
// Per-candidate-per-vector dot: strictly sequential fp32 fma chain over
// e = 0..31 (Eigen gebp order); score = (zz - 2*zc) + cc. Bit-identical to
// rounds 3/5. Two groups share all codebook smem loads (halves LDS/FMA).
template<int KP, int LV, bool WRITE_OUT>
__device__ __forceinline__ void quant_body2(
    int g0, const float* __restrict__ Z, const float* __restrict__ cb,
    float* __restrict__ zq_out, float* __restrict__ zq_chan,
    float* __restrict__ loss_slot, float* sC, float* sN)
{
  const int g1  = g0 + 1;
  const int l0  = g0 % LV, kp0 = (g0 / LV) % KP, b0 = g0 / (LV*KP);
  const int l1  = g1 % LV, kp1 = (g1 / LV) % KP, b1 = g1 / (LV*KP);
  const int p   = threadIdx.x;

  float z0[32], z1[32];
  float zz0 = 0.f, zz1 = 0.f;
  #pragma unroll
  for (int e=0;e<32;e++){
    float v0 = Z[((b0*1024 + e*(LV*KP) + l0*KP + kp0)*HW) + p];
    float v1 = Z[((b1*1024 + e*(LV*KP) + l1*KP + kp1)*HW) + p];
    z0[e] = v0; zz0 = fmaf(v0, v0, zz0);
    z1[e] = v1; zz1 = fmaf(v1, v1, zz1);
  }

  float best0 = 3.4e38f, best1 = 3.4e38f;
  int bestj0 = 0, bestj1 = 0;

  for (int ch=0; ch<1024; ch+=128){
    {
      const float4* cb4 = reinterpret_cast<const float4*>(cb + ch*32);
      float4* sC4 = reinterpret_cast<float4*>(sC);
      #pragma unroll
      for (int i=0;i<4;i++) sC4[threadIdx.x + i*256] = cb4[threadIdx.x + i*256];
    }
    if (threadIdx.x < 128) sN[threadIdx.x] = g_cnorm[ch + threadIdx.x];
    __syncthreads();

    for (int jj=0;jj<128;jj+=4){
      const float4* c0 = reinterpret_cast<const float4*>(&sC[(jj+0)*32]);
      const float4* c1 = reinterpret_cast<const float4*>(&sC[(jj+1)*32]);
      const float4* c2 = reinterpret_cast<const float4*>(&sC[(jj+2)*32]);
      const float4* c3 = reinterpret_cast<const float4*>(&sC[(jj+3)*32]);
      float a00=0.f, a01=0.f, a02=0.f, a03=0.f;   // vector 0 x 4 candidates
      float a10=0.f, a11=0.f, a12=0.f, a13=0.f;   // vector 1 x 4 candidates
      #pragma unroll
      for (int q=0;q<8;q++){
        float4 v0 = c0[q], v1 = c1[q], v2 = c2[q], v3 = c3[q];
        float vv0[4] = {v0.x,v0.y,v0.z,v0.w};
        float vv1[4] = {v1.x,v1.y,v1.z,v1.w};
        float vv2[4] = {v2.x,v2.y,v2.z,v2.w};
        float vv3[4] = {v3.x,v3.y,v3.z,v3.w};
        #pragma unroll
        for (int r=0;r<4;r++){
          float ze0 = z0[4*q+r];
          float ze1 = z1[4*q+r];
          a00 = fmaf(ze0, vv0[r], a00);
          a01 = fmaf(ze0, vv1[r], a01);
          a02 = fmaf(ze0, vv2[r], a02);
          a03 = fmaf(ze0, vv3[r], a03);
          a10 = fmaf(ze1, vv0[r], a10);
          a11 = fmaf(ze1, vv1[r], a11);
          a12 = fmaf(ze1, vv2[r], a12);
          a13 = fmaf(ze1, vv3[r], a13);
        }
      }
      float n0 = sN[jj+0], n1 = sN[jj+1], n2 = sN[jj+2], n3 = sN[jj+3];
      float s00 = (zz0 - 2.f*a00) + n0;
      float s01 = (zz0 - 2.f*a01) + n1;
      float s02 = (zz0 - 2.f*a02) + n2;
      float s03 = (zz0 - 2.f*a03) + n3;
      float s10 = (zz1 - 2.f*a10) + n0;
      float s11 = (zz1 - 2.f*a11) + n1;
      float s12 = (zz1 - 2.f*a12) + n2;
      float s13 = (zz1 - 2.f*a13) + n3;
      if (s00 < best0){ best0 = s00; bestj0 = ch + jj + 0; }
      if (s01 < best0){ best0 = s01; bestj0 = ch + jj + 1; }
      if (s02 < best0){ best0 = s02; bestj0 = ch + jj + 2; }
      if (s03 < best0){ best0 = s03; bestj0 = ch + jj + 3; }
      if (s10 < best1){ best1 = s10; bestj1 = ch + jj + 0; }
      if (s11 < best1){ best1 = s11; bestj1 = ch + jj + 1; }
      if (s12 < best1){ best1 = s12; bestj1 = ch + jj + 2; }
      if (s13 < best1){ best1 = s13; bestj1 = ch + jj + 3; }
    }
    __syncthreads();
  }

  // loss contributions (deterministic per-group sums, same order as R5)
  float s0 = best0, s1 = best1;
  #pragma unroll
  for (int o=16;o>0;o>>=1){
    s0 += __shfl_down_sync(0xffffffffu, s0, o);
    s1 += __shfl_down_sync(0xffffffffu, s1, o);
  }
  __shared__ float red0[8], red1[8];
  if ((threadIdx.x & 31) == 0){
    red0[threadIdx.x >> 5] = s0;
    red1[threadIdx.x >> 5] = s1;
  }
  __syncthreads();
  if (threadIdx.x == 0){
    float t0 = 0.f, t1 = 0.f;
    #pragma unroll
    for (int i=0;i<8;i++){ t0 += red0[i]; t1 += red1[i]; }
    loss_slot[g0] = t0;
    loss_slot[g1] = t1;
  }

  const float4* cb0 = reinterpret_cast<const float4*>(cb + bestj0*32);
  const float4* cb1 = reinterpret_cast<const float4*>(cb + bestj1*32);
  #pragma unroll
  for (int q=0;q<8;q++){
    float4 v4a = cb0[q];
    float4 v4b = cb1[q];
    float va[4] = {v4a.x, v4a.y, v4a.z, v4a.w};
    float vb[4] = {v4b.x, v4b.y, v4b.z, v4b.w};
    #pragma unroll
    for (int r=0;r<4;r++){
      int e = q*4 + r;
      zq_chan[(b0*1024 + e*(LV*KP) + l0*KP + kp0)*HW + p] = va[r];
      zq_chan[(b1*1024 + e*(LV*KP) + l1*KP + kp1)*HW + p] = vb[r];
      if (WRITE_OUT){
        zq_out[(((b0*32 + e)*(KP*HW)) + kp0*HW + p)*LV + l0] = va[r];
        zq_out[(((b1*32 + e)*(KP*HW)) + kp1*HW + p)*LV + l1] = vb[r];
      }
    }
  }
}

// one launch, both branches: blocks [0,256) = p pairs, [256,512) = n pairs
__global__ void __launch_bounds__(256)
quantize_all_kernel(const float* __restrict__ Zp, const float* __restrict__ Zn,
                    const float* __restrict__ cb,
                    float* __restrict__ zq_out,
                    float* __restrict__ zqp_chan, float* __restrict__ zqn_chan,
                    float* __restrict__ loss_part)
{
  __shared__ __align__(16) float sC[128*32];
  __shared__ float sN[128];
  if (blockIdx.x < 256){
    quant_body2<8,4,true >(2*blockIdx.x, Zp, cb, zq_out, zqp_chan, loss_part, sC, sN);
  } else {
    quant_body2<32,1,false>(2*(blockIdx.x-256), Zn, cb, nullptr, zqn_chan, loss_part + 512, sC, sN);
  }
}

// ---------------- deterministic loss finalize ----------------
__global__ void loss_final_kernel(float* __restrict__ out_loss){
  __shared__ float red[256];
  float s = 0.f;
  for (int i=threadIdx.x; i<1024; i+=256) s += g_loss_part[i];
  red[threadIdx.x] = s;
  __syncthreads();
  for (int o=128;o>0;o>>=1){
    if (threadIdx.x < o) red[threadIdx.x] += red[threadIdx.x + o];
    __syncthreads();
  }
  if (threadIdx.x == 0)
    *out_loss = 1.25f * red[0] / 4194304.f;
}

// ---------------- launch ----------------
extern "C" void kernel_launch(void* const* d_in, const int* in_sizes, int n_in,
                              void* d_out, int out_size)
{
  const float* x          = (const float*)d_in[0];
  const float* conv_in_w  = (const float*)d_in[1];
  const float* conv_in_b  = (const float*)d_in[2];
  const float* ln_p_w     = (const float*)d_in[3];
  const float* ln_p_b     = (const float*)d_in[4];
  const float* wp_in      = (const float*)d_in[5];
  const float* bp_in      = (const float*)d_in[6];
  const float* wp_out     = (const float*)d_in[7];
  const float* bp_out     = (const float*)d_in[8];
  const float* ln_n_w     = (const float*)d_in[9];
  const float* ln_n_b     = (const float*)d_in[10];
  const float* wn_in      = (const float*)d_in[11];
  const float* bn_in      = (const float*)d_in[12];
  const float* wn_out     = (const float*)d_in[13];
  const float* bn_out     = (const float*)d_in[14];
  const float* codebook   = (const float*)d_in[15];
  const float* conv_out_w = (const float*)d_in[16];
  const float* conv_out_b = (const float*)d_in[17];

  float* out      = (float*)d_out;               // [16,256,16,16]
  float* out_loss = out + 1048576;               // scalar
  float* out_zq   = out + 1048577;               // [16,32,2048,4]

  float *hbuf,*lnp,*lnn,*zp,*zn,*zqp,*zqn,*hcat,*lpart;
  cudaGetSymbolAddress((void**)&hbuf,  g_h);
  cudaGetSymbolAddress((void**)&lnp,   g_lnp);
  cudaGetSymbolAddress((void**)&lnn,   g_lnn);
  cudaGetSymbolAddress((void**)&zp,    g_zp);
  cudaGetSymbolAddress((void**)&zn,    g_zn);
  cudaGetSymbolAddress((void**)&zqp,   g_zqp);
  cudaGetSymbolAddress((void**)&zqn,   g_zqn);
  cudaGetSymbolAddress((void**)&hcat,  g_hcat);
  cudaGetSymbolAddress((void**)&lpart, g_loss_part);

  cnorm_kernel<<<4, 256>>>(codebook);

  // h = conv_in(silu(x))   M=256 -> grid (64,2,1)
  gemm_kernel<true,false><<<dim3(64, 2, 1), 256>>>(
      conv_in_w, conv_in_w, conv_in_b, conv_in_b, x, x, hbuf, hbuf,
      256, 256, 256, 0, 0);

  // layernorms (both branches)
  ln_stats_kernel<<<dim3(8, BATCH, 2), 256>>>(hbuf);
  ln_apply_kernel<<<dim3(8, BATCH, 2), 256>>>(hbuf, ln_p_w, ln_p_b, ln_n_w, ln_n_b, lnp, lnn);

  // z = silu(W_in @ ln + b)   M=1024 -> grid (64,8,2)
  gemm_kernel<false,true><<<dim3(64, 8, 2), 256>>>(
      wp_in, wn_in, bp_in, bn_in, lnp, lnn, zp, zn,
      128, 128, 1024, 0, 0);

  // VQ, both branches in one launch (2 vector-groups per block)
  quantize_all_kernel<<<512, 256>>>(zp, zn, codebook, out_zq, zqp, zqn, lpart);

  // hout = silu(W_out @ zq + b) into concat buffer   M=128 -> grid (64,1,2)
  gemm_kernel<false,true><<<dim3(64, 1, 2), 256>>>(
      wp_out, wn_out, bp_out, bn_out, zqp, zqn, hcat, hcat,
      1024, 1024, 256, 0, 128);

  // out = conv_out(silu(h_cat))   M=256 -> grid (64,2,1)
  gemm_kernel<true,false><<<dim3(64, 2, 1), 256>>>(
      conv_out_w, conv_out_w, conv_out_b, conv_out_b, hcat, hcat, out, out,
      256, 256, 256, 0, 0);

  loss_final_kernel<<<1, 256>>>(out_loss);
}

// round 10
// speedup vs baseline: 2.2752x; 1.2565x over previous
#include <cuda_runtime.h>
#include <cuda_bf16.h>
#include <math.h>
#include <stdint.h>

#define BATCH 16
#define HW 256
#define NT (BATCH*HW)   // 4096 total columns

// ---------------- scratch (no allocations allowed) ----------------
__device__ float g_h[BATCH*256*HW];      // conv_in output
__device__ float g_lnp[BATCH*128*HW];    // layernorm out (p)
__device__ float g_lnn[BATCH*128*HW];    // layernorm out (n)
__device__ float g_zp[BATCH*1024*HW];    // z_p (post-silu)
__device__ float g_zn[BATCH*1024*HW];    // z_n
__device__ float g_zqp[BATCH*1024*HW];   // zq_p channel layout
__device__ float g_zqn[BATCH*1024*HW];   // zq_n channel layout
__device__ float g_hcat[BATCH*256*HW];   // concat(hout_p, hout_n)
__device__ float g_cnorm[1024];
__device__ float g_loss_part[2048];      // per quantize-tile partials
__device__ float g_lnstat[2][BATCH][8][2]; // partial (sum, sumsq)
__device__ __align__(16) __nv_bfloat16 g_cb_hi[1024*32];
__device__ __align__(16) __nv_bfloat16 g_cb_lo[1024*32];

__device__ __forceinline__ float silu_f(float v){ return v / (1.f + expf(-v)); }

// ---------------- prep: codebook norms (exact chain) + bf16 hi/lo split ----
__global__ void prep_kernel(const float* __restrict__ cb){
  int j = blockIdx.x*blockDim.x + threadIdx.x;
  if (j < 1024){
    float s = 0.f;
    #pragma unroll
    for (int e=0;e<32;e++){
      float v = cb[j*32+e];
      s = fmaf(v,v,s);
      __nv_bfloat16 h = __float2bfloat16(v);
      float hf = __bfloat162float(h);
      __nv_bfloat16 l = __float2bfloat16(v - hf);
      g_cb_hi[j*32+e] = h;
      g_cb_lo[j*32+e] = l;
    }
    g_cnorm[j] = s;
  }
}

// ---------------- 1x1-conv GEMM, BM=128 BN=64 BK=16, scalar FFMA ----------
template<bool SILU_IN, bool SILU_OUT>
__global__ void __launch_bounds__(256)
gemm_kernel(const float* __restrict__ W0, const float* __restrict__ W1,
            const float* __restrict__ bias0, const float* __restrict__ bias1,
            const float* __restrict__ X0, const float* __restrict__ X1,
            float* __restrict__ Y0, float* __restrict__ Y1,
            int Kd, int CinTot, int OCtot, int oc_off0, int oc_off1)
{
  const float* W    = blockIdx.z ? W1 : W0;
  const float* bias = blockIdx.z ? bias1 : bias0;
  const float* X    = blockIdx.z ? X1 : X0;
  float*       Y    = blockIdx.z ? Y1 : Y0;
  const int oc_off  = blockIdx.z ? oc_off1 : oc_off0;

  __shared__ __align__(16) float As[16][128];
  __shared__ __align__(16) float Bs[16][64];
  const int tid = threadIdx.x;
  const int tx = tid & 15, ty = tid >> 4;
  const int j0 = blockIdx.x * 64;
  const int m0 = blockIdx.y * 128;
  const int b  = j0 >> 8;
  const int p0 = j0 & 255;

  float acc[8][4];
  #pragma unroll
  for (int i=0;i<8;i++)
    #pragma unroll
    for (int j=0;j<4;j++) acc[i][j] = 0.f;

  for (int k0=0;k0<Kd;k0+=16){
    #pragma unroll
    for (int i=0;i<8;i++){
      int e = tid + i*256;
      int m = e >> 4, k = e & 15;
      As[k][m] = W[(m0+m)*Kd + k0 + k];
    }
    #pragma unroll
    for (int i=0;i<4;i++){
      int e = tid + i*256;
      int k = e >> 6, j = e & 63;
      float v = X[((b*CinTot) + k0 + k)*HW + p0 + j];
      if (SILU_IN) v = silu_f(v);
      Bs[k][j] = v;
    }
    __syncthreads();
    #pragma unroll
    for (int kk=0;kk<16;kk++){
      float4 a0 = *reinterpret_cast<const float4*>(&As[kk][ty*8]);
      float4 a1 = *reinterpret_cast<const float4*>(&As[kk][ty*8+4]);
      float4 bv = *reinterpret_cast<const float4*>(&Bs[kk][tx*4]);
      float av[8] = {a0.x,a0.y,a0.z,a0.w,a1.x,a1.y,a1.z,a1.w};
      float bb[4] = {bv.x,bv.y,bv.z,bv.w};
      #pragma unroll
      for (int i=0;i<8;i++)
        #pragma unroll
        for (int j=0;j<4;j++)
          acc[i][j] = fmaf(av[i], bb[j], acc[i][j]);
    }
    __syncthreads();
  }

  #pragma unroll
  for (int i=0;i<8;i++){
    int m = m0 + ty*8 + i;
    float bb = bias[m];
    float4 o;
    o.x = acc[i][0] + bb; o.y = acc[i][1] + bb;
    o.z = acc[i][2] + bb; o.w = acc[i][3] + bb;
    if (SILU_OUT){
      o.x = silu_f(o.x); o.y = silu_f(o.y); o.z = silu_f(o.z); o.w = silu_f(o.w);
    }
    *reinterpret_cast<float4*>(&Y[((b*OCtot) + oc_off + m)*HW + p0 + tx*4]) = o;
  }
}

// ---------------- layernorm: stats then apply, both branches via grid.z ----
__global__ void ln_stats_kernel(const float* __restrict__ H){
  const int c  = blockIdx.x;
  const int b  = blockIdx.y;
  const int br = blockIdx.z;
  const float* base = H + (b*256 + br*128)*HW + c*4096;
  float s = 0.f, sq = 0.f;
  for (int i=threadIdx.x; i<4096; i+=256){
    float v = silu_f(base[i]);
    s += v; sq = fmaf(v, v, sq);
  }
  __shared__ float rs[8], rq[8];
  #pragma unroll
  for (int o=16;o>0;o>>=1){
    s  += __shfl_down_sync(0xffffffffu, s,  o);
    sq += __shfl_down_sync(0xffffffffu, sq, o);
  }
  int wid = threadIdx.x >> 5, lid = threadIdx.x & 31;
  if (lid == 0){ rs[wid] = s; rq[wid] = sq; }
  __syncthreads();
  if (threadIdx.x == 0){
    float ts = 0.f, tq = 0.f;
    #pragma unroll
    for (int i=0;i<8;i++){ ts += rs[i]; tq += rq[i]; }
    g_lnstat[br][b][c][0] = ts;
    g_lnstat[br][b][c][1] = tq;
  }
}

__global__ void ln_apply_kernel(const float* __restrict__ H,
                                const float* __restrict__ wp, const float* __restrict__ bp,
                                const float* __restrict__ wn, const float* __restrict__ bn,
                                float* __restrict__ outp, float* __restrict__ outn)
{
  const int c  = blockIdx.x;
  const int b  = blockIdx.y;
  const int br = blockIdx.z;
  float s = 0.f, sq = 0.f;
  #pragma unroll
  for (int i=0;i<8;i++){ s += g_lnstat[br][b][i][0]; sq += g_lnstat[br][b][i][1]; }
  float mu   = s * (1.f/32768.f);
  float var  = sq * (1.f/32768.f) - mu*mu;
  float rstd = rsqrtf(var + 1e-5f);
  const float* base = H + (b*256 + br*128)*HW + c*4096;
  const float* w  = (br ? wn : wp) + c*4096;
  const float* bb = (br ? bn : bp) + c*4096;
  float* ob = (br ? outn : outp) + b*32768 + c*4096;
  for (int i=threadIdx.x; i<4096; i+=256){
    float v = silu_f(base[i]);
    ob[i] = (v - mu) * rstd * w[i] + bb[i];
  }
}

// ---------------- tensor-core VQ via mma.sync (bf16 hi/lo 3-term) ----------
// Block = 128 threads (4 warps) = 128 vectors. Warp w owns vectors
// [w*32, w*32+32) as two m16 tiles. 8 candidate tiles of 128 streamed via
// smem. zc via mma.sync m16n8k16: hi*hi + lo*hi + hi*lo (|err| ~3e-8).
// Approx top-2 per vector, then EXACT sequential-fp32 rescoring (R5 chain,
// strict <, ascending index) reproduces the scalar argmin.
#define MMA16816(d0,d1,d2,d3,a0,a1,a2,a3,b0,b1) \
  asm volatile("mma.sync.aligned.m16n8k16.row.col.f32.bf16.bf16.f32 " \
      "{%0,%1,%2,%3}, {%4,%5,%6,%7}, {%8,%9}, {%0,%1,%2,%3};" \
      : "+f"(d0), "+f"(d1), "+f"(d2), "+f"(d3) \
      : "r"(a0), "r"(a1), "r"(a2), "r"(a3), "r"(b0), "r"(b1))

#define RPAD 40   // padded row length (bf16) for bank-conflict-free frags

__global__ void __launch_bounds__(128)
quantize_tc_kernel(const float* __restrict__ Zp, const float* __restrict__ Zn,
                   const float* __restrict__ cb,
                   float* __restrict__ zq_out,
                   float* __restrict__ zqp_chan, float* __restrict__ zqn_chan,
                   float* __restrict__ loss_part)
{
  __shared__ __align__(16) __nv_bfloat16 s_hi[128*RPAD];
  __shared__ __align__(16) __nv_bfloat16 s_lo[128*RPAD];
  __shared__ float sCC[128];
  __shared__ int2  sTOP[128];

  const int tid = threadIdx.x;
  const int wid = tid >> 5;
  const int lane = tid & 31;
  const int g   = lane >> 2;    // group id (0..7)
  const int tig = lane & 3;     // thread in group
  const int bx  = blockIdx.x;

  const bool isP = (bx < 1024);
  const int local = isP ? bx : bx - 1024;
  const int grp = local >> 1, h = local & 1;
  int l, kp, b;
  if (isP){ l = grp & 3; kp = (grp >> 2) & 7; b = grp >> 5; }
  else    { l = 0;       kp = grp & 31;       b = grp >> 5; }
  const int gidx = isP ? (l*8 + kp) : kp;
  const float* Z = isP ? Zp : Zn;
  float* zq_chan = isP ? zqp_chan : zqn_chan;
  const int p = h*128 + tid;

  // ---- load my vector (exact fp32) + zz chain ----
  float z[32];
  float zz = 0.f;
  #pragma unroll
  for (int e=0;e<32;e++){
    float v = Z[((b*1024 + e*32 + gidx)*HW) + p];
    z[e] = v; zz = fmaf(v, v, zz);
  }

  // ---- stage bf16 hi/lo of z into smem (row = my vector) ----
  {
    uint32_t hiw[16], low[16];
    #pragma unroll
    for (int i=0;i<16;i++){
      float v0 = z[2*i], v1 = z[2*i+1];
      __nv_bfloat16 h0 = __float2bfloat16(v0), h1 = __float2bfloat16(v1);
      float f0 = __bfloat162float(h0), f1 = __bfloat162float(h1);
      __nv_bfloat16 l0 = __float2bfloat16(v0 - f0), l1 = __float2bfloat16(v1 - f1);
      hiw[i] = ((uint32_t)__bfloat16_as_ushort(h1) << 16) | (uint32_t)__bfloat16_as_ushort(h0);
      low[i] = ((uint32_t)__bfloat16_as_ushort(l1) << 16) | (uint32_t)__bfloat16_as_ushort(l0);
    }
    uint4* dH = reinterpret_cast<uint4*>(s_hi + tid*RPAD);
    uint4* dL = reinterpret_cast<uint4*>(s_lo + tid*RPAD);
    const uint4* sH = reinterpret_cast<const uint4*>(hiw);
    const uint4* sL = reinterpret_cast<const uint4*>(low);
    #pragma unroll
    for (int i=0;i<4;i++){ dH[i] = sH[i]; dL[i] = sL[i]; }
  }
  __syncthreads();

  // ---- load loop-invariant A fragments (2 m-tiles x 2 k-steps, hi+lo) ----
  // mma m16n8k16 A-frag: a0=(g, c..c+1) a1=(g+8, c) a2=(g, c+8) a3=(g+8, c+8), c=tig*2
  uint32_t aH[2][2][4], aL[2][2][4];
  #pragma unroll
  for (int m=0;m<2;m++){
    #pragma unroll
    for (int s=0;s<2;s++){
      int r0 = wid*32 + m*16 + g;
      int k0 = s*16 + tig*2;
      aH[m][s][0] = *reinterpret_cast<const uint32_t*>(s_hi + r0*RPAD + k0);
      aH[m][s][1] = *reinterpret_cast<const uint32_t*>(s_hi + (r0+8)*RPAD + k0);
      aH[m][s][2] = *reinterpret_cast<const uint32_t*>(s_hi + r0*RPAD + k0 + 8);
      aH[m][s][3] = *reinterpret_cast<const uint32_t*>(s_hi + (r0+8)*RPAD + k0 + 8);
      aL[m][s][0] = *reinterpret_cast<const uint32_t*>(s_lo + r0*RPAD + k0);
      aL[m][s][1] = *reinterpret_cast<const uint32_t*>(s_lo + (r0+8)*RPAD + k0);
      aL[m][s][2] = *reinterpret_cast<const uint32_t*>(s_lo + r0*RPAD + k0 + 8);
      aL[m][s][3] = *reinterpret_cast<const uint32_t*>(s_lo + (r0+8)*RPAD + k0 + 8);
    }
  }
  __syncthreads();   // done with z staging; reuse s_hi/s_lo for candidates

  // ---- per-thread top-2 for the 4 D-rows I hold (m-tile x row-half) ----
  float tb1[4], tb2[4];
  int   tj1[4], tj2[4];
  #pragma unroll
  for (int i=0;i<4;i++){ tb1[i]=3.4e38f; tb2[i]=3.4e38f; tj1[i]=0; tj2[i]=0; }

  for (int t=0; t<8; t++){
    const int base_n = t*128;
    // load candidate tile (row = candidate): 32 bf16 hi + lo, cc
    {
      const uint4* srcH = reinterpret_cast<const uint4*>(g_cb_hi + (base_n + tid)*32);
      const uint4* srcL = reinterpret_cast<const uint4*>(g_cb_lo + (base_n + tid)*32);
      uint4* dH = reinterpret_cast<uint4*>(s_hi + tid*RPAD);
      uint4* dL = reinterpret_cast<uint4*>(s_lo + tid*RPAD);
      #pragma unroll
      for (int i=0;i<4;i++){ dH[i] = srcH[i]; dL[i] = srcL[i]; }
      sCC[tid] = g_cnorm[base_n + tid];
    }
    __syncthreads();

    #pragma unroll 4
    for (int sub=0; sub<16; sub++){
      // B-frags: col-major k16n8: b0=(k=tig*2.., n=g), b1=(k+8, n=g)
      const int bn = sub*8 + g;
      uint32_t bh0 = *reinterpret_cast<const uint32_t*>(s_hi + bn*RPAD + tig*2);
      uint32_t bh1 = *reinterpret_cast<const uint32_t*>(s_hi + bn*RPAD + tig*2 + 8);
      uint32_t bh2 = *reinterpret_cast<const uint32_t*>(s_hi + bn*RPAD + 16 + tig*2);
      uint32_t bh3 = *reinterpret_cast<const uint32_t*>(s_hi + bn*RPAD + 16 + tig*2 + 8);
      uint32_t bl0 = *reinterpret_cast<const uint32_t*>(s_lo + bn*RPAD + tig*2);
      uint32_t bl1 = *reinterpret_cast<const uint32_t*>(s_lo + bn*RPAD + tig*2 + 8);
      uint32_t bl2 = *reinterpret_cast<const uint32_t*>(s_lo + bn*RPAD + 16 + tig*2);
      uint32_t bl3 = *reinterpret_cast<const uint32_t*>(s_lo + bn*RPAD + 16 + tig*2 + 8);

      const int j0 = base_n + sub*8 + tig*2;
      const float cc0 = sCC[sub*8 + tig*2];
      const float cc1 = sCC[sub*8 + tig*2 + 1];

      #pragma unroll
      for (int m=0;m<2;m++){
        float d0=0.f, d1=0.f, d2=0.f, d3=0.f;
        MMA16816(d0,d1,d2,d3, aH[m][0][0],aH[m][0][1],aH[m][0][2],aH[m][0][3], bh0,bh1);
        MMA16816(d0,d1,d2,d3, aH[m][1][0],aH[m][1][1],aH[m][1][2],aH[m][1][3], bh2,bh3);
        MMA16816(d0,d1,d2,d3, aL[m][0][0],aL[m][0][1],aL[m][0][2],aL[m][0][3], bh0,bh1);
        MMA16816(d0,d1,d2,d3, aL[m][1][0],aL[m][1][1],aL[m][1][2],aL[m][1][3], bh2,bh3);
        MMA16816(d0,d1,d2,d3, aH[m][0][0],aH[m][0][1],aH[m][0][2],aH[m][0][3], bl0,bl1);
        MMA16816(d0,d1,d2,d3, aH[m][1][0],aH[m][1][1],aH[m][1][2],aH[m][1][3], bl2,bl3);
        // D layout: d0=(g, tig*2) d1=(g, tig*2+1) d2=(g+8, tig*2) d3=(g+8, +1)
        float s00 = fmaf(-2.f, d0, cc0);
        float s01 = fmaf(-2.f, d1, cc1);
        float s10 = fmaf(-2.f, d2, cc0);
        float s11 = fmaf(-2.f, d3, cc1);
        int ia = m*2, ib = m*2+1;
        if (s00 < tb1[ia]){ tb2[ia]=tb1[ia]; tj2[ia]=tj1[ia]; tb1[ia]=s00; tj1[ia]=j0; }
        else if (s00 < tb2[ia]){ tb2[ia]=s00; tj2[ia]=j0; }
        if (s01 < tb1[ia]){ tb2[ia]=tb1[ia]; tj2[ia]=tj1[ia]; tb1[ia]=s01; tj1[ia]=j0+1; }
        else if (s01 < tb2[ia]){ tb2[ia]=s01; tj2[ia]=j0+1; }
        if (s10 < tb1[ib]){ tb2[ib]=tb1[ib]; tj2[ib]=tj1[ib]; tb1[ib]=s10; tj1[ib]=j0; }
        else if (s10 < tb2[ib]){ tb2[ib]=s10; tj2[ib]=j0; }
        if (s11 < tb1[ib]){ tb2[ib]=tb1[ib]; tj2[ib]=tj1[ib]; tb1[ib]=s11; tj1[ib]=j0+1; }
        else if (s11 < tb2[ib]){ tb2[ib]=s11; tj2[ib]=j0+1; }
      }
    }
    __syncthreads();
  }

  // ---- merge top-2 across the 4 lanes sharing each row; write (j1,j2) ----
  #pragma unroll
  for (int idx=0; idx<4; idx++){
    float b1v = tb1[idx], b2v = tb2[idx];
    int   j1v = tj1[idx], j2v = tj2[idx];
    #pragma unroll
    for (int st=1; st<4; st<<=1){
      float o1 = __shfl_xor_sync(0xffffffffu, b1v, st);
      int  oj1 = __shfl_xor_sync(0xffffffffu, j1v, st);
      float o2 = __shfl_xor_sync(0xffffffffu, b2v, st);
      int  oj2 = __shfl_xor_sync(0xffffffffu, j2v, st);
      if (o1 < b1v){
        if (b1v < o2){ b2v = b1v; j2v = j1v; } else { b2v = o2; j2v = oj2; }
        b1v = o1; j1v = oj1;
      } else if (o1 < b2v){ b2v = o1; j2v = oj1; }
    }
    if (tig == 0){
      int vloc = wid*32 + (idx>>1)*16 + g + (idx&1)*8;
      sTOP[vloc] = make_int2(j1v, j2v);
    }
  }
  __syncthreads();

  // ---- exact rescoring of the two candidates (ascending index, strict <) --
  int2 t2 = sTOP[tid];
  int jlo = t2.x < t2.y ? t2.x : t2.y;
  int jhi = t2.x < t2.y ? t2.y : t2.x;
  float best; int bestj;
  {
    const float4* C = reinterpret_cast<const float4*>(cb + jlo*32);
    float a = 0.f;
    #pragma unroll
    for (int q=0;q<8;q++){
      float4 c = C[q];
      a = fmaf(z[4*q+0], c.x, a);
      a = fmaf(z[4*q+1], c.y, a);
      a = fmaf(z[4*q+2], c.z, a);
      a = fmaf(z[4*q+3], c.w, a);
    }
    best = (zz - 2.f*a) + g_cnorm[jlo];
    bestj = jlo;
  }
  if (jhi != jlo){
    const float4* C = reinterpret_cast<const float4*>(cb + jhi*32);
    float a = 0.f;
    #pragma unroll
    for (int q=0;q<8;q++){
      float4 c = C[q];
      a = fmaf(z[4*q+0], c.x, a);
      a = fmaf(z[4*q+1], c.y, a);
      a = fmaf(z[4*q+2], c.z, a);
      a = fmaf(z[4*q+3], c.w, a);
    }
    float s = (zz - 2.f*a) + g_cnorm[jhi];
    if (s < best){ best = s; bestj = jhi; }
  }

  // ---- deterministic per-tile loss partial ----
  {
    float s = best;
    #pragma unroll
    for (int o=16;o>0;o>>=1) s += __shfl_down_sync(0xffffffffu, s, o);
    __shared__ float red[4];
    if (lane == 0) red[wid] = s;
    __syncthreads();
    if (tid == 0){
      float tsum = 0.f;
      #pragma unroll
      for (int i=0;i<4;i++) tsum += red[i];
      loss_part[bx] = tsum;
    }
  }

  // ---- scatter winning code ----
  const float4* cbest = reinterpret_cast<const float4*>(cb + bestj*32);
  #pragma unroll
  for (int q=0;q<8;q++){
    float4 v4 = cbest[q];
    float vv[4] = {v4.x, v4.y, v4.z, v4.w};
    #pragma unroll
    for (int r=0;r<4;r++){
      int e = q*4 + r;
      zq_chan[(b*1024 + e*32 + gidx)*HW + p] = vv[r];
      if (isP)
        zq_out[(((b*32 + e)*2048) + kp*256 + p)*4 + l] = vv[r];
    }
  }
}

// ---------------- deterministic loss finalize ----------------
__global__ void loss_final_kernel(float* __restrict__ out_loss){
  __shared__ float red[256];
  float s = 0.f;
  for (int i=threadIdx.x; i<2048; i+=256) s += g_loss_part[i];
  red[threadIdx.x] = s;
  __syncthreads();
  for (int o=128;o>0;o>>=1){
    if (threadIdx.x < o) red[threadIdx.x] += red[threadIdx.x + o];
    __syncthreads();
  }
  if (threadIdx.x == 0)
    *out_loss = 1.25f * red[0] / 4194304.f;
}

// ---------------- launch ----------------
extern "C" void kernel_launch(void* const* d_in, const int* in_sizes, int n_in,
                              void* d_out, int out_size)
{
  const float* x          = (const float*)d_in[0];
  const float* conv_in_w  = (const float*)d_in[1];
  const float* conv_in_b  = (const float*)d_in[2];
  const float* ln_p_w     = (const float*)d_in[3];
  const float* ln_p_b     = (const float*)d_in[4];
  const float* wp_in      = (const float*)d_in[5];
  const float* bp_in      = (const float*)d_in[6];
  const float* wp_out     = (const float*)d_in[7];
  const float* bp_out     = (const float*)d_in[8];
  const float* ln_n_w     = (const float*)d_in[9];
  const float* ln_n_b     = (const float*)d_in[10];
  const float* wn_in      = (const float*)d_in[11];
  const float* bn_in      = (const float*)d_in[12];
  const float* wn_out     = (const float*)d_in[13];
  const float* bn_out     = (const float*)d_in[14];
  const float* codebook   = (const float*)d_in[15];
  const float* conv_out_w = (const float*)d_in[16];
  const float* conv_out_b = (const float*)d_in[17];

  float* out      = (float*)d_out;               // [16,256,16,16]
  float* out_loss = out + 1048576;               // scalar
  float* out_zq   = out + 1048577;               // [16,32,2048,4]

  float *hbuf,*lnp,*lnn,*zp,*zn,*zqp,*zqn,*hcat,*lpart;
  cudaGetSymbolAddress((void**)&hbuf,  g_h);
  cudaGetSymbolAddress((void**)&lnp,   g_lnp);
  cudaGetSymbolAddress((void**)&lnn,   g_lnn);
  cudaGetSymbolAddress((void**)&zp,    g_zp);
  cudaGetSymbolAddress((void**)&zn,    g_zn);
  cudaGetSymbolAddress((void**)&zqp,   g_zqp);
  cudaGetSymbolAddress((void**)&zqn,   g_zqn);
  cudaGetSymbolAddress((void**)&hcat,  g_hcat);
  cudaGetSymbolAddress((void**)&lpart, g_loss_part);

  prep_kernel<<<4, 256>>>(codebook);

  // h = conv_in(silu(x))
  gemm_kernel<true,false><<<dim3(64, 2, 1), 256>>>(
      conv_in_w, conv_in_w, conv_in_b, conv_in_b, x, x, hbuf, hbuf,
      256, 256, 256, 0, 0);

  // layernorms (both branches)
  ln_stats_kernel<<<dim3(8, BATCH, 2), 256>>>(hbuf);
  ln_apply_kernel<<<dim3(8, BATCH, 2), 256>>>(hbuf, ln_p_w, ln_p_b, ln_n_w, ln_n_b, lnp, lnn);

  // z = silu(W_in @ ln + b)
  gemm_kernel<false,true><<<dim3(64, 8, 2), 256>>>(
      wp_in, wn_in, bp_in, bn_in, lnp, lnn, zp, zn,
      128, 128, 1024, 0, 0);

  // VQ via mma.sync tensor cores: 2048 tiles of 128 vectors
  quantize_tc_kernel<<<2048, 128>>>(zp, zn, codebook, out_zq, zqp, zqn, lpart);

  // hout = silu(W_out @ zq + b) into concat buffer
  gemm_kernel<false,true><<<dim3(64, 1, 2), 256>>>(
      wp_out, wn_out, bp_out, bn_out, zqp, zqn, hcat, hcat,
      1024, 1024, 256, 0, 128);

  // out = conv_out(silu(h_cat))
  gemm_kernel<true,false><<<dim3(64, 2, 1), 256>>>(
      conv_out_w, conv_out_w, conv_out_b, conv_out_b, hcat, hcat, out, out,
      256, 256, 256, 0, 0);

  loss_final_kernel<<<1, 256>>>(out_loss);
}

// round 15
// speedup vs baseline: 2.5414x; 1.1170x over previous
#include <cuda_runtime.h>
#include <cuda_bf16.h>
#include <math.h>
#include <stdint.h>

#define BATCH 16
#define HW 256
#define NT (BATCH*HW)   // 4096 total columns

// ---------------- scratch (no allocations allowed) ----------------
__device__ float g_h[BATCH*256*HW];        // conv_in output [b][256][256]
__device__ float g_lnstat[2][BATCH][8][2];
__device__ float g_ln[2][BATCH*128*HW];    // layernorm out fp32 [b][128][256]
__device__ float g_z[2][BATCH*1024*HW];    // z fp32 [b][1024][256] per branch
__device__ __align__(16) __nv_bfloat16 g_zqhi[2][1024*4096];  // zq [c][4096]
__device__ __align__(16) __nv_bfloat16 g_zqlo[2][1024*4096];
__device__ __align__(16) __nv_bfloat16 g_hchi[256*4096];      // silu(hcat) [c][4096]
__device__ __align__(16) __nv_bfloat16 g_hclo[256*4096];
__device__ __align__(16) __nv_bfloat16 g_wTout_hi[2][1024*128];
__device__ __align__(16) __nv_bfloat16 g_wTout_lo[2][1024*128];
__device__ __align__(16) __nv_bfloat16 g_wTco_hi[256*256];
__device__ __align__(16) __nv_bfloat16 g_wTco_lo[256*256];
__device__ float g_cnorm[1024];
__device__ float g_loss_part[2048];
__device__ __align__(16) __nv_bfloat16 g_cb_hi[1024*32];
__device__ __align__(16) __nv_bfloat16 g_cb_lo[1024*32];

__device__ __forceinline__ float silu_f(float v){ return v / (1.f + expf(-v)); }
__device__ __forceinline__ void split_bf16(float v, __nv_bfloat16& h, __nv_bfloat16& l){
  h = __float2bfloat16(v);
  l = __float2bfloat16(v - __bfloat162float(h));
}
__device__ __forceinline__ uint32_t smem_to_u32(const void* smem_ptr) {
  uint32_t addr;
  asm("{ .reg .u64 tmp; cvta.to.shared.u64 tmp, %1; cvt.u32.u64 %0, tmp; }"
      : "=r"(addr) : "l"(smem_ptr));
  return addr;
}

#define MMA16816(d0,d1,d2,d3,a0,a1,a2,a3,b0,b1) \
  asm volatile("mma.sync.aligned.m16n8k16.row.col.f32.bf16.bf16.f32 " \
      "{%0,%1,%2,%3}, {%4,%5,%6,%7}, {%8,%9}, {%0,%1,%2,%3};" \
      : "+f"(d0), "+f"(d1), "+f"(d2), "+f"(d3) \
      : "r"(a0), "r"(a1), "r"(a2), "r"(a3), "r"(b0), "r"(b1))
#define LDSM_X4(r0,r1,r2,r3,addr) \
  asm volatile("ldmatrix.sync.aligned.m8n8.x4.shared.b16 {%0,%1,%2,%3}, [%4];" \
      : "=r"(r0),"=r"(r1),"=r"(r2),"=r"(r3) : "r"(addr))
#define LDSM_X4_T(r0,r1,r2,r3,addr) \
  asm volatile("ldmatrix.sync.aligned.m8n8.x4.trans.shared.b16 {%0,%1,%2,%3}, [%4];" \
      : "=r"(r0),"=r"(r1),"=r"(r2),"=r"(r3) : "r"(addr))

// ---------------- prep: codebook norms + cb split ----------------
__global__ void prep_cb_kernel(const float* __restrict__ cb){
  int j = blockIdx.x*blockDim.x + threadIdx.x;
  if (j < 1024){
    float s = 0.f;
    #pragma unroll
    for (int e=0;e<32;e++){
      float v = cb[j*32+e];
      s = fmaf(v,v,s);
      __nv_bfloat16 h, l; split_bf16(v, h, l);
      g_cb_hi[j*32+e] = h;
      g_cb_lo[j*32+e] = l;
    }
    g_cnorm[j] = s;
  }
}

// ---------------- prep: weight transpose + hi/lo split (wout, conv_out) ---
__global__ void prep_w_kernel(const float* __restrict__ wpo, const float* __restrict__ wno,
                              const float* __restrict__ wco){
  int i = blockIdx.x*blockDim.x + threadIdx.x;
  __nv_bfloat16 h, l;
  if (i < 131072){                 // wp_out [128][1024] -> [k*128+m]
    int m = i >> 10, k = i & 1023;
    split_bf16(wpo[i], h, l);
    g_wTout_hi[0][k*128+m] = h; g_wTout_lo[0][k*128+m] = l;
  } else if (i < 262144){          // wn_out
    int j = i - 131072;
    int m = j >> 10, k = j & 1023;
    split_bf16(wno[j], h, l);
    g_wTout_hi[1][k*128+m] = h; g_wTout_lo[1][k*128+m] = l;
  } else if (i < 327680){          // conv_out_w [256][256] -> [k*256+m]
    int j = i - 262144;
    int m = j >> 8, k = j & 255;
    split_bf16(wco[j], h, l);
    g_wTco_hi[k*256+m] = h; g_wTco_lo[k*256+m] = l;
  }
}

// ---------------- scalar FFMA GEMM (bit-exact; conv_in + wp_in/wn_in) -----
// BM=128 BN=64 BK=16, 8x4 regs/thread; accumulation strictly sequential in k.
template<bool SILU_IN, bool SILU_OUT>
__global__ void __launch_bounds__(256)
gemm_kernel(const float* __restrict__ W0, const float* __restrict__ W1,
            const float* __restrict__ bias0, const float* __restrict__ bias1,
            const float* __restrict__ X0, const float* __restrict__ X1,
            float* __restrict__ Y0, float* __restrict__ Y1,
            int Kd, int CinTot, int OCtot)
{
  const float* W    = blockIdx.z ? W1 : W0;
  const float* bias = blockIdx.z ? bias1 : bias0;
  const float* X    = blockIdx.z ? X1 : X0;
  float*       Y    = blockIdx.z ? Y1 : Y0;

  __shared__ __align__(16) float As[16][128];
  __shared__ __align__(16) float Bs[16][64];
  const int tid = threadIdx.x;
  const int tx = tid & 15, ty = tid >> 4;
  const int j0 = blockIdx.x * 64;
  const int m0 = blockIdx.y * 128;
  const int b  = j0 >> 8;
  const int p0 = j0 & 255;

  float acc[8][4];
  #pragma unroll
  for (int i=0;i<8;i++)
    #pragma unroll
    for (int j=0;j<4;j++) acc[i][j] = 0.f;

  for (int k0=0;k0<Kd;k0+=16){
    #pragma unroll
    for (int i=0;i<8;i++){
      int e = tid + i*256;
      int m = e >> 4, k = e & 15;
      As[k][m] = W[(m0+m)*Kd + k0 + k];
    }
    #pragma unroll
    for (int i=0;i<4;i++){
      int e = tid + i*256;
      int k = e >> 6, j = e & 63;
      float v = X[((b*CinTot) + k0 + k)*HW + p0 + j];
      if (SILU_IN) v = silu_f(v);
      Bs[k][j] = v;
    }
    __syncthreads();
    #pragma unroll
    for (int kk=0;kk<16;kk++){
      float4 a0 = *reinterpret_cast<const float4*>(&As[kk][ty*8]);
      float4 a1 = *reinterpret_cast<const float4*>(&As[kk][ty*8+4]);
      float4 bv = *reinterpret_cast<const float4*>(&Bs[kk][tx*4]);
      float av[8] = {a0.x,a0.y,a0.z,a0.w,a1.x,a1.y,a1.z,a1.w};
      float bb[4] = {bv.x,bv.y,bv.z,bv.w};
      #pragma unroll
      for (int i=0;i<8;i++)
        #pragma unroll
        for (int j=0;j<4;j++)
          acc[i][j] = fmaf(av[i], bb[j], acc[i][j]);
    }
    __syncthreads();
  }

  #pragma unroll
  for (int i=0;i<8;i++){
    int m = m0 + ty*8 + i;
    float bb = bias[m];
    float4 o;
    o.x = acc[i][0] + bb; o.y = acc[i][1] + bb;
    o.z = acc[i][2] + bb; o.w = acc[i][3] + bb;
    if (SILU_OUT){
      o.x = silu_f(o.x); o.y = silu_f(o.y); o.z = silu_f(o.z); o.w = silu_f(o.w);
    }
    *reinterpret_cast<float4*>(&Y[((b*OCtot) + m)*HW + p0 + tx*4]) = o;
  }
}

// ---------------- layernorm: stats then apply (fp32 out) ------------------
__global__ void ln_stats_kernel(const float* __restrict__ H){
  const int c  = blockIdx.x;
  const int b  = blockIdx.y;
  const int br = blockIdx.z;
  const float* base = H + (b*256 + br*128)*HW + c*4096;
  float s = 0.f, sq = 0.f;
  for (int i=threadIdx.x; i<4096; i+=256){
    float v = silu_f(base[i]);
    s += v; sq = fmaf(v, v, sq);
  }
  __shared__ float rs[8], rq[8];
  #pragma unroll
  for (int o=16;o>0;o>>=1){
    s  += __shfl_down_sync(0xffffffffu, s,  o);
    sq += __shfl_down_sync(0xffffffffu, sq, o);
  }
  int wid = threadIdx.x >> 5, lid = threadIdx.x & 31;
  if (lid == 0){ rs[wid] = s; rq[wid] = sq; }
  __syncthreads();
  if (threadIdx.x == 0){
    float ts = 0.f, tq = 0.f;
    #pragma unroll
    for (int i=0;i<8;i++){ ts += rs[i]; tq += rq[i]; }
    g_lnstat[br][b][c][0] = ts;
    g_lnstat[br][b][c][1] = tq;
  }
}

__global__ void ln_apply_kernel(const float* __restrict__ H,
                                const float* __restrict__ wp, const float* __restrict__ bp,
                                const float* __restrict__ wn, const float* __restrict__ bn)
{
  const int c  = blockIdx.x;
  const int b  = blockIdx.y;
  const int br = blockIdx.z;
  float s = 0.f, sq = 0.f;
  #pragma unroll
  for (int i=0;i<8;i++){ s += g_lnstat[br][b][i][0]; sq += g_lnstat[br][b][i][1]; }
  float mu   = s * (1.f/32768.f);
  float var  = sq * (1.f/32768.f) - mu*mu;
  float rstd = rsqrtf(var + 1e-5f);
  const float* base = H + (b*256 + br*128)*HW + c*4096;
  const float* w  = (br ? wn : wp) + c*4096;
  const float* bb = (br ? bn : bp) + c*4096;
  float* ob = g_ln[br] + b*32768 + c*4096;
  for (int i=threadIdx.x; i<4096; i+=256){
    float v = silu_f(base[i]);
    ob[i] = (v - mu) * rstd * w[i] + bb[i];
  }
}

// ---------------- tensor-core VQ (mma.sync + ldmatrix; exact z in) --------
#define RPAD 40   // 80B rows: 16B-aligned, conflict-free for ldmatrix

__global__ void __launch_bounds__(128)
quantize_tc_kernel(const float* __restrict__ Zp, const float* __restrict__ Zn,
                   const float* __restrict__ cb,
                   float* __restrict__ zq_out,
                   float* __restrict__ loss_part)
{
  __shared__ __align__(16) __nv_bfloat16 s_hi[128*RPAD];
  __shared__ __align__(16) __nv_bfloat16 s_lo[128*RPAD];
  __shared__ float sCC[128];
  __shared__ int2  sTOP[128];

  const int tid = threadIdx.x;
  const int wid = tid >> 5;
  const int lane = tid & 31;
  const int g   = lane >> 2;
  const int tig = lane & 3;
  const int bx  = blockIdx.x;

  const bool isP = (bx < 1024);
  const int local = isP ? bx : bx - 1024;
  const int grp = local >> 1, h = local & 1;
  int l, kp, b;
  if (isP){ l = grp & 3; kp = (grp >> 2) & 7; b = grp >> 5; }
  else    { l = 0;       kp = grp & 31;       b = grp >> 5; }
  const int gidx = isP ? (l*8 + kp) : kp;
  const float* Z = isP ? Zp : Zn;
  __nv_bfloat16* zqh = isP ? g_zqhi[0] : g_zqhi[1];
  __nv_bfloat16* zql = isP ? g_zqlo[0] : g_zqlo[1];
  const int p = h*128 + tid;
  const int col = b*256 + p;   // column in [c][4096] zq layout

  // ---- load my vector (exact fp32, [b][1024][256] layout) + zz chain ----
  float z[32];
  float zz = 0.f;
  #pragma unroll
  for (int e=0;e<32;e++){
    float v = Z[((b*1024 + e*32 + gidx)*HW) + p];
    z[e] = v; zz = fmaf(v, v, zz);
  }

  // ---- stage bf16 hi/lo of z into smem (row = my vector) ----
  {
    uint32_t hiw[16], low[16];
    #pragma unroll
    for (int i=0;i<16;i++){
      __nv_bfloat16 h0,l0,h1,l1;
      split_bf16(z[2*i], h0, l0);
      split_bf16(z[2*i+1], h1, l1);
      hiw[i] = ((uint32_t)__bfloat16_as_ushort(h1) << 16) | (uint32_t)__bfloat16_as_ushort(h0);
      low[i] = ((uint32_t)__bfloat16_as_ushort(l1) << 16) | (uint32_t)__bfloat16_as_ushort(l0);
    }
    uint4* dH = reinterpret_cast<uint4*>(s_hi + tid*RPAD);
    uint4* dL = reinterpret_cast<uint4*>(s_lo + tid*RPAD);
    const uint4* sH = reinterpret_cast<const uint4*>(hiw);
    const uint4* sL = reinterpret_cast<const uint4*>(low);
    #pragma unroll
    for (int i=0;i<4;i++){ dH[i] = sH[i]; dL[i] = sL[i]; }
  }
  __syncthreads();

  // ---- loop-invariant A fragments (2 m-tiles x 2 k-steps, hi+lo) ----
  uint32_t aH[2][2][4], aL[2][2][4];
  #pragma unroll
  for (int m=0;m<2;m++){
    #pragma unroll
    for (int s=0;s<2;s++){
      int r0 = wid*32 + m*16 + g;
      int k0 = s*16 + tig*2;
      aH[m][s][0] = *reinterpret_cast<const uint32_t*>(s_hi + r0*RPAD + k0);
      aH[m][s][1] = *reinterpret_cast<const uint32_t*>(s_hi + (r0+8)*RPAD + k0);
      aH[m][s][2] = *reinterpret_cast<const uint32_t*>(s_hi + r0*RPAD + k0 + 8);
      aH[m][s][3] = *reinterpret_cast<const uint32_t*>(s_hi + (r0+8)*RPAD + k0 + 8);
      aL[m][s][0] = *reinterpret_cast<const uint32_t*>(s_lo + r0*RPAD + k0);
      aL[m][s][1] = *reinterpret_cast<const uint32_t*>(s_lo + (r0+8)*RPAD + k0);
      aL[m][s][2] = *reinterpret_cast<const uint32_t*>(s_lo + r0*RPAD + k0 + 8);
      aL[m][s][3] = *reinterpret_cast<const uint32_t*>(s_lo + (r0+8)*RPAD + k0 + 8);
    }
  }
  __syncthreads();

  const uint32_t sHiB = smem_to_u32(s_hi), sLoB = smem_to_u32(s_lo);
  const uint32_t laneB = (((uint32_t)(lane&7))*RPAD + (uint32_t)(lane>>3)*8)*2;

  float tb1[4], tb2[4];
  int   tj1[4], tj2[4];
  #pragma unroll
  for (int i=0;i<4;i++){ tb1[i]=3.4e38f; tb2[i]=3.4e38f; tj1[i]=0; tj2[i]=0; }

  for (int t=0; t<8; t++){
    const int base_n = t*128;
    {
      const uint4* srcH = reinterpret_cast<const uint4*>(g_cb_hi + (base_n + tid)*32);
      const uint4* srcL = reinterpret_cast<const uint4*>(g_cb_lo + (base_n + tid)*32);
      uint4* dH = reinterpret_cast<uint4*>(s_hi + tid*RPAD);
      uint4* dL = reinterpret_cast<uint4*>(s_lo + tid*RPAD);
      #pragma unroll
      for (int i=0;i<4;i++){ dH[i] = srcH[i]; dL[i] = srcL[i]; }
      sCC[tid] = g_cnorm[base_n + tid];
    }
    __syncthreads();

    #pragma unroll 4
    for (int sub=0; sub<16; sub++){
      uint32_t bh0,bh1,bh2,bh3, bl0,bl1,bl2,bl3;
      uint32_t off = (uint32_t)sub*(8*RPAD*2) + laneB;
      LDSM_X4(bh0,bh1,bh2,bh3, sHiB + off);
      LDSM_X4(bl0,bl1,bl2,bl3, sLoB + off);

      const int j0 = base_n + sub*8 + tig*2;
      const float cc0 = sCC[sub*8 + tig*2];
      const float cc1 = sCC[sub*8 + tig*2 + 1];

      #pragma unroll
      for (int m=0;m<2;m++){
        float d0=0.f, d1=0.f, d2=0.f, d3=0.f;
        MMA16816(d0,d1,d2,d3, aH[m][0][0],aH[m][0][1],aH[m][0][2],aH[m][0][3], bh0,bh1);
        MMA16816(d0,d1,d2,d3, aH[m][1][0],aH[m][1][1],aH[m][1][2],aH[m][1][3], bh2,bh3);
        MMA16816(d0,d1,d2,d3, aL[m][0][0],aL[m][0][1],aL[m][0][2],aL[m][0][3], bh0,bh1);
        MMA16816(d0,d1,d2,d3, aL[m][1][0],aL[m][1][1],aL[m][1][2],aL[m][1][3], bh2,bh3);
        MMA16816(d0,d1,d2,d3, aH[m][0][0],aH[m][0][1],aH[m][0][2],aH[m][0][3], bl0,bl1);
        MMA16816(d0,d1,d2,d3, aH[m][1][0],aH[m][1][1],aH[m][1][2],aH[m][1][3], bl2,bl3);
        float s00 = fmaf(-2.f, d0, cc0);
        float s01 = fmaf(-2.f, d1, cc1);
        float s10 = fmaf(-2.f, d2, cc0);
        float s11 = fmaf(-2.f, d3, cc1);
        int ia = m*2, ib = m*2+1;
        if (s00 < tb1[ia]){ tb2[ia]=tb1[ia]; tj2[ia]=tj1[ia]; tb1[ia]=s00; tj1[ia]=j0; }
        else if (s00 < tb2[ia]){ tb2[ia]=s00; tj2[ia]=j0; }
        if (s01 < tb1[ia]){ tb2[ia]=tb1[ia]; tj2[ia]=tj1[ia]; tb1[ia]=s01; tj1[ia]=j0+1; }
        else if (s01 < tb2[ia]){ tb2[ia]=s01; tj2[ia]=j0+1; }
        if (s10 < tb1[ib]){ tb2[ib]=tb1[ib]; tj2[ib]=tj1[ib]; tb1[ib]=s10; tj1[ib]=j0; }
        else if (s10 < tb2[ib]){ tb2[ib]=s10; tj2[ib]=j0; }
        if (s11 < tb1[ib]){ tb2[ib]=tb1[ib]; tj2[ib]=tj1[ib]; tb1[ib]=s11; tj1[ib]=j0+1; }
        else if (s11 < tb2[ib]){ tb2[ib]=s11; tj2[ib]=j0+1; }
      }
    }
    __syncthreads();
  }

  // ---- merge top-2 across the 4 lanes sharing each row ----
  #pragma unroll
  for (int idx=0; idx<4; idx++){
    float b1v = tb1[idx], b2v = tb2[idx];
    int   j1v = tj1[idx], j2v = tj2[idx];
    #pragma unroll
    for (int st=1; st<4; st<<=1){
      float o1 = __shfl_xor_sync(0xffffffffu, b1v, st);
      int  oj1 = __shfl_xor_sync(0xffffffffu, j1v, st);
      float o2 = __shfl_xor_sync(0xffffffffu, b2v, st);
      int  oj2 = __shfl_xor_sync(0xffffffffu, j2v, st);
      if (o1 < b1v){
        if (b1v < o2){ b2v = b1v; j2v = j1v; } else { b2v = o2; j2v = oj2; }
        b1v = o1; j1v = oj1;
      } else if (o1 < b2v){ b2v = o1; j2v = oj1; }
    }
    if (tig == 0){
      int vloc = wid*32 + (idx>>1)*16 + g + (idx&1)*8;
      sTOP[vloc] = make_int2(j1v, j2v);
    }
  }
  __syncthreads();

  // ---- exact rescoring (strict <, ascending index) ----
  int2 t2 = sTOP[tid];
  int jlo = t2.x < t2.y ? t2.x : t2.y;
  int jhi = t2.x < t2.y ? t2.y : t2.x;
  float best; int bestj;
  {
    const float4* C = reinterpret_cast<const float4*>(cb + jlo*32);
    float a = 0.f;
    #pragma unroll
    for (int q=0;q<8;q++){
      float4 c = C[q];
      a = fmaf(z[4*q+0], c.x, a);
      a = fmaf(z[4*q+1], c.y, a);
      a = fmaf(z[4*q+2], c.z, a);
      a = fmaf(z[4*q+3], c.w, a);
    }
    best = (zz - 2.f*a) + g_cnorm[jlo];
    bestj = jlo;
  }
  if (jhi != jlo){
    const float4* C = reinterpret_cast<const float4*>(cb + jhi*32);
    float a = 0.f;
    #pragma unroll
    for (int q=0;q<8;q++){
      float4 c = C[q];
      a = fmaf(z[4*q+0], c.x, a);
      a = fmaf(z[4*q+1], c.y, a);
      a = fmaf(z[4*q+2], c.z, a);
      a = fmaf(z[4*q+3], c.w, a);
    }
    float s = (zz - 2.f*a) + g_cnorm[jhi];
    if (s < best){ best = s; bestj = jhi; }
  }

  // ---- deterministic per-tile loss partial ----
  {
    float s = best;
    #pragma unroll
    for (int o=16;o>0;o>>=1) s += __shfl_down_sync(0xffffffffu, s, o);
    __shared__ float red[4];
    if (lane == 0) red[wid] = s;
    __syncthreads();
    if (tid == 0){
      float tsum = 0.f;
      #pragma unroll
      for (int i=0;i<4;i++) tsum += red[i];
      loss_part[bx] = tsum;
    }
  }

  // ---- scatter winning code: zq hi/lo [c][4096] + fp32 zq_out (p branch) -
  const float4* cbest = reinterpret_cast<const float4*>(cb + bestj*32);
  #pragma unroll
  for (int q=0;q<8;q++){
    float4 v4 = cbest[q];
    float vv[4] = {v4.x, v4.y, v4.z, v4.w};
    #pragma unroll
    for (int r=0;r<4;r++){
      int e = q*4 + r;
      __nv_bfloat16 hh, ll; split_bf16(vv[r], hh, ll);
      zqh[(e*32 + gidx)*4096 + col] = hh;
      zql[(e*32 + gidx)*4096 + col] = ll;
      if (isP)
        zq_out[(((b*32 + e)*2048) + kp*256 + p)*4 + l] = vv[r];
    }
  }
}

// ---------------- tensor GEMM (wout / conv_out; no argmin downstream) -----
// OMODE 1: store silu(silu(acc+b)) hi/lo [c][4096] (conv_out's input).
// OMODE 2: final out [b][256][16][16] fp32.
#define WROW 136
#define XROW 72

template<int OMODE>
__global__ void __launch_bounds__(256)
tgemm_kernel(const __nv_bfloat16* __restrict__ WT_hi0, const __nv_bfloat16* __restrict__ WT_hi1,
             const __nv_bfloat16* __restrict__ WT_lo0, const __nv_bfloat16* __restrict__ WT_lo1,
             const float* __restrict__ bias0, const float* __restrict__ bias1,
             const __nv_bfloat16* __restrict__ Xhi0, const __nv_bfloat16* __restrict__ Xhi1,
             const __nv_bfloat16* __restrict__ Xlo0, const __nv_bfloat16* __restrict__ Xlo1,
             float* __restrict__ Yf,
             __nv_bfloat16* __restrict__ Yhi, __nv_bfloat16* __restrict__ Ylo,
             int Kd, int M, int oc_off0, int oc_off1)
{
  const int br = blockIdx.z;
  const __nv_bfloat16* WT_hi = br ? WT_hi1 : WT_hi0;
  const __nv_bfloat16* WT_lo = br ? WT_lo1 : WT_lo0;
  const float* bias = br ? bias1 : bias0;
  const __nv_bfloat16* Xhi = br ? Xhi1 : Xhi0;
  const __nv_bfloat16* Xlo = br ? Xlo1 : Xlo0;
  const int oc_off = br ? oc_off1 : oc_off0;

  __shared__ __align__(16) __nv_bfloat16 sWhi[32*WROW];
  __shared__ __align__(16) __nv_bfloat16 sWlo[32*WROW];
  __shared__ __align__(16) __nv_bfloat16 sXhi[32*XROW];
  __shared__ __align__(16) __nv_bfloat16 sXlo[32*XROW];

  const int tid = threadIdx.x;
  const int warp = tid >> 5, lane = tid & 31;
  const int n0 = blockIdx.x*64, m0 = blockIdx.y*128;
  const int mw = warp*16;
  const int t8 = tid & 7, kk = tid >> 3;

  const uint32_t sWhiB = smem_to_u32(sWhi), sWloB = smem_to_u32(sWlo);
  const uint32_t sXhiB = smem_to_u32(sXhi), sXloB = smem_to_u32(sXlo);
  const uint32_t aRow = (lane&7) + ((lane>>4)&1)*8;
  const uint32_t aCol = mw + ((lane>>3)&1)*8;
  const uint32_t bOffBase = lane*(XROW*2);

  float acc[8][4];
  #pragma unroll
  for (int g=0;g<8;g++)
    #pragma unroll
    for (int i=0;i<4;i++) acc[g][i] = 0.f;

  #pragma unroll 1
  for (int k0=0;k0<Kd;k0+=32){
    {
      const uint4* sh = reinterpret_cast<const uint4*>(WT_hi + (k0+kk)*M + m0 + t8*16);
      const uint4* sl = reinterpret_cast<const uint4*>(WT_lo + (k0+kk)*M + m0 + t8*16);
      uint4* dh = reinterpret_cast<uint4*>(sWhi + kk*WROW + t8*16);
      uint4* dl = reinterpret_cast<uint4*>(sWlo + kk*WROW + t8*16);
      dh[0] = sh[0]; dh[1] = sh[1];
      dl[0] = sl[0]; dl[1] = sl[1];
    }
    {
      *reinterpret_cast<uint4*>(sXhi + kk*XROW + t8*8) =
        *reinterpret_cast<const uint4*>(Xhi + (k0+kk)*4096 + n0 + t8*8);
      *reinterpret_cast<uint4*>(sXlo + kk*XROW + t8*8) =
        *reinterpret_cast<const uint4*>(Xlo + (k0+kk)*4096 + n0 + t8*8);
    }
    __syncthreads();

    uint32_t aH[2][4], aL[2][4];
    #pragma unroll
    for (int s=0;s<2;s++){
      uint32_t off = ((s*16 + aRow)*WROW + aCol)*2;
      LDSM_X4_T(aH[s][0],aH[s][1],aH[s][2],aH[s][3], sWhiB + off);
      LDSM_X4_T(aL[s][0],aL[s][1],aL[s][2],aL[s][3], sWloB + off);
    }
    #pragma unroll
    for (int g=0;g<8;g++){
      uint32_t bh0,bh1,bh2,bh3, bl0,bl1,bl2,bl3;
      LDSM_X4_T(bh0,bh1,bh2,bh3, sXhiB + bOffBase + g*16);
      LDSM_X4_T(bl0,bl1,bl2,bl3, sXloB + bOffBase + g*16);
      MMA16816(acc[g][0],acc[g][1],acc[g][2],acc[g][3], aH[0][0],aH[0][1],aH[0][2],aH[0][3], bh0,bh1);
      MMA16816(acc[g][0],acc[g][1],acc[g][2],acc[g][3], aH[1][0],aH[1][1],aH[1][2],aH[1][3], bh2,bh3);
      MMA16816(acc[g][0],acc[g][1],acc[g][2],acc[g][3], aL[0][0],aL[0][1],aL[0][2],aL[0][3], bh0,bh1);
      MMA16816(acc[g][0],acc[g][1],acc[g][2],acc[g][3], aL[1][0],aL[1][1],aL[1][2],aL[1][3], bh2,bh3);
      MMA16816(acc[g][0],acc[g][1],acc[g][2],acc[g][3], aH[0][0],aH[0][1],aH[0][2],aH[0][3], bl0,bl1);
      MMA16816(acc[g][0],acc[g][1],acc[g][2],acc[g][3], aH[1][0],aH[1][1],aH[1][2],aH[1][3], bl2,bl3);
    }
    __syncthreads();
  }

  const int r0 = m0 + mw + (lane>>2);
  const int r1 = r0 + 8;
  const float bb0 = bias[r0], bb1 = bias[r1];
  #pragma unroll
  for (int g=0;g<8;g++){
    int j = n0 + g*8 + (lane&3)*2;
    float v00 = acc[g][0] + bb0, v01 = acc[g][1] + bb0;
    float v10 = acc[g][2] + bb1, v11 = acc[g][3] + bb1;
    if (OMODE == 1){
      // hout = silu(acc+b); conv_out input = silu(hout): apply silu TWICE.
      float w00 = silu_f(silu_f(v00)), w01 = silu_f(silu_f(v01));
      float w10 = silu_f(silu_f(v10)), w11 = silu_f(silu_f(v11));
      __nv_bfloat16 h0,l0,h1,l1;
      split_bf16(w00,h0,l0); split_bf16(w01,h1,l1);
      uint32_t ph = ((uint32_t)__bfloat16_as_ushort(h1)<<16) | __bfloat16_as_ushort(h0);
      uint32_t pl = ((uint32_t)__bfloat16_as_ushort(l1)<<16) | __bfloat16_as_ushort(l0);
      *reinterpret_cast<uint32_t*>(&Yhi[(oc_off + r0)*4096 + j]) = ph;
      *reinterpret_cast<uint32_t*>(&Ylo[(oc_off + r0)*4096 + j]) = pl;
      split_bf16(w10,h0,l0); split_bf16(w11,h1,l1);
      ph = ((uint32_t)__bfloat16_as_ushort(h1)<<16) | __bfloat16_as_ushort(h0);
      pl = ((uint32_t)__bfloat16_as_ushort(l1)<<16) | __bfloat16_as_ushort(l0);
      *reinterpret_cast<uint32_t*>(&Yhi[(oc_off + r1)*4096 + j]) = ph;
      *reinterpret_cast<uint32_t*>(&Ylo[(oc_off + r1)*4096 + j]) = pl;
    } else {
      int bb = j >> 8, pp = j & 255;
      *reinterpret_cast<float2*>(&Yf[bb*65536 + r0*256 + pp]) = make_float2(v00, v01);
      *reinterpret_cast<float2*>(&Yf[bb*65536 + r1*256 + pp]) = make_float2(v10, v11);
    }
  }
}

// ---------------- deterministic loss finalize ----------------
__global__ void loss_final_kernel(float* __restrict__ out_loss){
  __shared__ float red[256];
  float s = 0.f;
  for (int i=threadIdx.x; i<2048; i+=256) s += g_loss_part[i];
  red[threadIdx.x] = s;
  __syncthreads();
  for (int o=128;o>0;o>>=1){
    if (threadIdx.x < o) red[threadIdx.x] += red[threadIdx.x + o];
    __syncthreads();
  }
  if (threadIdx.x == 0)
    *out_loss = 1.25f * red[0] / 4194304.f;
}

// ---------------- launch ----------------
extern "C" void kernel_launch(void* const* d_in, const int* in_sizes, int n_in,
                              void* d_out, int out_size)
{
  const float* x          = (const float*)d_in[0];
  const float* conv_in_w  = (const float*)d_in[1];
  const float* conv_in_b  = (const float*)d_in[2];
  const float* ln_p_w     = (const float*)d_in[3];
  const float* ln_p_b     = (const float*)d_in[4];
  const float* wp_in      = (const float*)d_in[5];
  const float* bp_in      = (const float*)d_in[6];
  const float* wp_out     = (const float*)d_in[7];
  const float* bp_out     = (const float*)d_in[8];
  const float* ln_n_w     = (const float*)d_in[9];
  const float* ln_n_b     = (const float*)d_in[10];
  const float* wn_in      = (const float*)d_in[11];
  const float* bn_in      = (const float*)d_in[12];
  const float* wn_out     = (const float*)d_in[13];
  const float* bn_out     = (const float*)d_in[14];
  const float* codebook   = (const float*)d_in[15];
  const float* conv_out_w = (const float*)d_in[16];
  const float* conv_out_b = (const float*)d_in[17];

  float* out      = (float*)d_out;               // [16,256,16,16]
  float* out_loss = out + 1048576;               // scalar
  float* out_zq   = out + 1048577;               // [16,32,2048,4]

  float *hbuf, *lnbuf, *zbuf, *lpart;
  __nv_bfloat16 *wTout_hi, *wTout_lo, *wTco_hi, *wTco_lo;
  __nv_bfloat16 *zqhi, *zqlo, *hchi, *hclo;
  cudaGetSymbolAddress((void**)&hbuf,  g_h);
  cudaGetSymbolAddress((void**)&lnbuf, g_ln);
  cudaGetSymbolAddress((void**)&zbuf,  g_z);
  cudaGetSymbolAddress((void**)&lpart, g_loss_part);
  cudaGetSymbolAddress((void**)&wTout_hi, g_wTout_hi);
  cudaGetSymbolAddress((void**)&wTout_lo, g_wTout_lo);
  cudaGetSymbolAddress((void**)&wTco_hi,  g_wTco_hi);
  cudaGetSymbolAddress((void**)&wTco_lo,  g_wTco_lo);
  cudaGetSymbolAddress((void**)&zqhi,  g_zqhi);
  cudaGetSymbolAddress((void**)&zqlo,  g_zqlo);
  cudaGetSymbolAddress((void**)&hchi,  g_hchi);
  cudaGetSymbolAddress((void**)&hclo,  g_hclo);

  // proper device pointers for the per-branch slices (NOT raw symbol refs!)
  float* ln0 = lnbuf;
  float* ln1 = lnbuf + BATCH*128*HW;     // 524288
  float* z0  = zbuf;
  float* z1  = zbuf + BATCH*1024*HW;     // 4194304

  prep_cb_kernel<<<4, 256>>>(codebook);
  prep_w_kernel<<<1280, 256>>>(wp_out, wn_out, conv_out_w);

  // h = conv_in(silu(x)) — scalar fp32 (exact chain)
  gemm_kernel<true,false><<<dim3(64, 2, 1), 256>>>(
      conv_in_w, conv_in_w, conv_in_b, conv_in_b, x, x, hbuf, hbuf,
      256, 256, 256);

  // layernorms -> fp32 [b][128][256] (exact chain)
  ln_stats_kernel<<<dim3(8, BATCH, 2), 256>>>(hbuf);
  ln_apply_kernel<<<dim3(8, BATCH, 2), 256>>>(hbuf, ln_p_w, ln_p_b, ln_n_w, ln_n_b);

  // z = silu(W_in @ ln + b) — scalar fp32 GEMM (exact chain, bit-identical z)
  gemm_kernel<false,true><<<dim3(64, 8, 2), 256>>>(
      wp_in, wn_in, bp_in, bn_in,
      ln0, ln1, z0, z1,
      128, 128, 1024);

  // VQ via tensor cores + exact rescue (argmin exact)
  quantize_tc_kernel<<<2048, 128>>>(z0, z1, codebook, out_zq, lpart);

  // hout chain: silu(silu(W_out @ zq + b)) hi/lo [c][4096] — tensor (tolerant)
  tgemm_kernel<1><<<dim3(64, 1, 2), 256>>>(
      wTout_hi, wTout_hi + 131072, wTout_lo, wTout_lo + 131072,
      bp_out, bn_out,
      zqhi, zqhi + 4194304, zqlo, zqlo + 4194304,
      nullptr, hchi, hclo,
      1024, 128, 0, 128);

  // out = conv_out(silu(h_cat)) — tensor (tolerant)
  tgemm_kernel<2><<<dim3(64, 2, 1), 256>>>(
      wTco_hi, wTco_hi, wTco_lo, wTco_lo,
      conv_out_b, conv_out_b,
      hchi, hchi, hclo, hclo,
      out, nullptr, nullptr,
      256, 256, 0, 0);

  loss_final_kernel<<<1, 256>>>(out_loss);
}

// round 16
// speedup vs baseline: 2.5730x; 1.0124x over previous
#include <cuda_runtime.h>
#include <cuda_bf16.h>
#include <cuda_fp16.h>
#include <math.h>
#include <stdint.h>

#define BATCH 16
#define HW 256
#define NT (BATCH*HW)   // 4096 total columns

// ---------------- scratch (no allocations allowed) ----------------
__device__ float g_h[BATCH*256*HW];        // conv_in output [b][256][256]
__device__ float g_lnstat[2][BATCH][8][2];
__device__ float g_ln[2][BATCH*128*HW];    // layernorm out fp32 [b][128][256]
__device__ float g_z[2][BATCH*1024*HW];    // z fp32 [b][1024][256] per branch
__device__ __align__(16) __nv_bfloat16 g_zqhi[2][1024*4096];  // zq [c][4096]
__device__ __align__(16) __nv_bfloat16 g_zqlo[2][1024*4096];
__device__ __align__(16) __nv_bfloat16 g_hchi[256*4096];      // silu(hcat) [c][4096]
__device__ __align__(16) __nv_bfloat16 g_hclo[256*4096];
__device__ __align__(16) __nv_bfloat16 g_wTout_hi[2][1024*128];
__device__ __align__(16) __nv_bfloat16 g_wTout_lo[2][1024*128];
__device__ __align__(16) __nv_bfloat16 g_wTco_hi[256*256];
__device__ __align__(16) __nv_bfloat16 g_wTco_lo[256*256];
__device__ float g_cnorm[1024];
__device__ float g_loss_part[2048];
__device__ __align__(16) __half g_cb_h[1024*32];   // codebook fp16 (hi only)

__device__ __forceinline__ float silu_f(float v){ return v / (1.f + expf(-v)); }
__device__ __forceinline__ void split_bf16(float v, __nv_bfloat16& h, __nv_bfloat16& l){
  h = __float2bfloat16(v);
  l = __float2bfloat16(v - __bfloat162float(h));
}
__device__ __forceinline__ uint32_t smem_to_u32(const void* smem_ptr) {
  uint32_t addr;
  asm("{ .reg .u64 tmp; cvta.to.shared.u64 tmp, %1; cvt.u32.u64 %0, tmp; }"
      : "=r"(addr) : "l"(smem_ptr));
  return addr;
}

#define MMA16816(d0,d1,d2,d3,a0,a1,a2,a3,b0,b1) \
  asm volatile("mma.sync.aligned.m16n8k16.row.col.f32.bf16.bf16.f32 " \
      "{%0,%1,%2,%3}, {%4,%5,%6,%7}, {%8,%9}, {%0,%1,%2,%3};" \
      : "+f"(d0), "+f"(d1), "+f"(d2), "+f"(d3) \
      : "r"(a0), "r"(a1), "r"(a2), "r"(a3), "r"(b0), "r"(b1))
#define MMA16816H(d0,d1,d2,d3,a0,a1,a2,a3,b0,b1) \
  asm volatile("mma.sync.aligned.m16n8k16.row.col.f32.f16.f16.f32 " \
      "{%0,%1,%2,%3}, {%4,%5,%6,%7}, {%8,%9}, {%0,%1,%2,%3};" \
      : "+f"(d0), "+f"(d1), "+f"(d2), "+f"(d3) \
      : "r"(a0), "r"(a1), "r"(a2), "r"(a3), "r"(b0), "r"(b1))
#define LDSM_X4(r0,r1,r2,r3,addr) \
  asm volatile("ldmatrix.sync.aligned.m8n8.x4.shared.b16 {%0,%1,%2,%3}, [%4];" \
      : "=r"(r0),"=r"(r1),"=r"(r2),"=r"(r3) : "r"(addr))
#define LDSM_X4_T(r0,r1,r2,r3,addr) \
  asm volatile("ldmatrix.sync.aligned.m8n8.x4.trans.shared.b16 {%0,%1,%2,%3}, [%4];" \
      : "=r"(r0),"=r"(r1),"=r"(r2),"=r"(r3) : "r"(addr))

// ---------------- prep: codebook norms (exact chain) + fp16 codebook ------
__global__ void prep_cb_kernel(const float* __restrict__ cb){
  int j = blockIdx.x*blockDim.x + threadIdx.x;
  if (j < 1024){
    float s = 0.f;
    #pragma unroll
    for (int e=0;e<32;e++){
      float v = cb[j*32+e];
      s = fmaf(v,v,s);
      g_cb_h[j*32+e] = __float2half_rn(v);
    }
    g_cnorm[j] = s;
  }
}

// ---------------- prep: weight transpose + hi/lo split (wout, conv_out) ---
__global__ void prep_w_kernel(const float* __restrict__ wpo, const float* __restrict__ wno,
                              const float* __restrict__ wco){
  int i = blockIdx.x*blockDim.x + threadIdx.x;
  __nv_bfloat16 h, l;
  if (i < 131072){                 // wp_out [128][1024] -> [k*128+m]
    int m = i >> 10, k = i & 1023;
    split_bf16(wpo[i], h, l);
    g_wTout_hi[0][k*128+m] = h; g_wTout_lo[0][k*128+m] = l;
  } else if (i < 262144){          // wn_out
    int j = i - 131072;
    int m = j >> 10, k = j & 1023;
    split_bf16(wno[j], h, l);
    g_wTout_hi[1][k*128+m] = h; g_wTout_lo[1][k*128+m] = l;
  } else if (i < 327680){          // conv_out_w [256][256] -> [k*256+m]
    int j = i - 262144;
    int m = j >> 8, k = j & 255;
    split_bf16(wco[j], h, l);
    g_wTco_hi[k*256+m] = h; g_wTco_lo[k*256+m] = l;
  }
}

// ---------------- scalar FFMA GEMM (bit-exact; conv_in + wp_in/wn_in) -----
// BM=128 BN=64 BK=32; per-output accumulation strictly sequential in k
// (same k-order as all passing rounds -> bit-identical z).
template<bool SILU_IN, bool SILU_OUT>
__global__ void __launch_bounds__(256)
gemm_kernel(const float* __restrict__ W0, const float* __restrict__ W1,
            const float* __restrict__ bias0, const float* __restrict__ bias1,
            const float* __restrict__ X0, const float* __restrict__ X1,
            float* __restrict__ Y0, float* __restrict__ Y1,
            int Kd, int CinTot, int OCtot)
{
  const float* W    = blockIdx.z ? W1 : W0;
  const float* bias = blockIdx.z ? bias1 : bias0;
  const float* X    = blockIdx.z ? X1 : X0;
  float*       Y    = blockIdx.z ? Y1 : Y0;

  __shared__ __align__(16) float As[32][128];
  __shared__ __align__(16) float Bs[32][64];
  const int tid = threadIdx.x;
  const int tx = tid & 15, ty = tid >> 4;
  const int j0 = blockIdx.x * 64;
  const int m0 = blockIdx.y * 128;
  const int b  = j0 >> 8;
  const int p0 = j0 & 255;

  float acc[8][4];
  #pragma unroll
  for (int i=0;i<8;i++)
    #pragma unroll
    for (int j=0;j<4;j++) acc[i][j] = 0.f;

  for (int k0=0;k0<Kd;k0+=32){
    #pragma unroll
    for (int i=0;i<16;i++){
      int e = tid + i*256;          // 4096 = 128 m x 32 k
      int m = e >> 5, k = e & 31;
      As[k][m] = W[(m0+m)*Kd + k0 + k];
    }
    #pragma unroll
    for (int i=0;i<8;i++){
      int e = tid + i*256;          // 2048 = 32 k x 64 j
      int k = e >> 6, j = e & 63;
      float v = X[((b*CinTot) + k0 + k)*HW + p0 + j];
      if (SILU_IN) v = silu_f(v);
      Bs[k][j] = v;
    }
    __syncthreads();
    #pragma unroll
    for (int kk=0;kk<32;kk++){
      float4 a0 = *reinterpret_cast<const float4*>(&As[kk][ty*8]);
      float4 a1 = *reinterpret_cast<const float4*>(&As[kk][ty*8+4]);
      float4 bv = *reinterpret_cast<const float4*>(&Bs[kk][tx*4]);
      float av[8] = {a0.x,a0.y,a0.z,a0.w,a1.x,a1.y,a1.z,a1.w};
      float bb[4] = {bv.x,bv.y,bv.z,bv.w};
      #pragma unroll
      for (int i=0;i<8;i++)
        #pragma unroll
        for (int j=0;j<4;j++)
          acc[i][j] = fmaf(av[i], bb[j], acc[i][j]);
    }
    __syncthreads();
  }

  #pragma unroll
  for (int i=0;i<8;i++){
    int m = m0 + ty*8 + i;
    float bb = bias[m];
    float4 o;
    o.x = acc[i][0] + bb; o.y = acc[i][1] + bb;
    o.z = acc[i][2] + bb; o.w = acc[i][3] + bb;
    if (SILU_OUT){
      o.x = silu_f(o.x); o.y = silu_f(o.y); o.z = silu_f(o.z); o.w = silu_f(o.w);
    }
    *reinterpret_cast<float4*>(&Y[((b*OCtot) + m)*HW + p0 + tx*4]) = o;
  }
}

// ---------------- layernorm: stats then apply (fp32 out) ------------------
__global__ void ln_stats_kernel(const float* __restrict__ H){
  const int c  = blockIdx.x;
  const int b  = blockIdx.y;
  const int br = blockIdx.z;
  const float* base = H + (b*256 + br*128)*HW + c*4096;
  float s = 0.f, sq = 0.f;
  for (int i=threadIdx.x; i<4096; i+=256){
    float v = silu_f(base[i]);
    s += v; sq = fmaf(v, v, sq);
  }
  __shared__ float rs[8], rq[8];
  #pragma unroll
  for (int o=16;o>0;o>>=1){
    s  += __shfl_down_sync(0xffffffffu, s,  o);
    sq += __shfl_down_sync(0xffffffffu, sq, o);
  }
  int wid = threadIdx.x >> 5, lid = threadIdx.x & 31;
  if (lid == 0){ rs[wid] = s; rq[wid] = sq; }
  __syncthreads();
  if (threadIdx.x == 0){
    float ts = 0.f, tq = 0.f;
    #pragma unroll
    for (int i=0;i<8;i++){ ts += rs[i]; tq += rq[i]; }
    g_lnstat[br][b][c][0] = ts;
    g_lnstat[br][b][c][1] = tq;
  }
}

__global__ void ln_apply_kernel(const float* __restrict__ H,
                                const float* __restrict__ wp, const float* __restrict__ bp,
                                const float* __restrict__ wn, const float* __restrict__ bn)
{
  const int c  = blockIdx.x;
  const int b  = blockIdx.y;
  const int br = blockIdx.z;
  float s = 0.f, sq = 0.f;
  #pragma unroll
  for (int i=0;i<8;i++){ s += g_lnstat[br][b][i][0]; sq += g_lnstat[br][b][i][1]; }
  float mu   = s * (1.f/32768.f);
  float var  = sq * (1.f/32768.f) - mu*mu;
  float rstd = rsqrtf(var + 1e-5f);
  const float* base = H + (b*256 + br*128)*HW + c*4096;
  const float* w  = (br ? wn : wp) + c*4096;
  const float* bb = (br ? bn : bp) + c*4096;
  float* ob = g_ln[br] + b*32768 + c*4096;
  for (int i=threadIdx.x; i<4096; i+=256){
    float v = silu_f(base[i]);
    ob[i] = (v - mu) * rstd * w[i] + bb[i];
  }
}

// ---------------- tensor-core VQ (fp16 2-term + exact rescue) -------------
// zc_approx = zh*ch + (zl*2048)*ch * 2^-11   (zl scaled into fp16 normal range)
// score error ~6e-8; exact fp32 rescoring of approx top-2 gives the exact
// argmin (strict <, ascending index). z is the bit-exact scalar-GEMM output.
#define RPAD 40   // 80B rows: 16B-aligned, conflict-free for ldmatrix
#define ZL_SCALE 2048.0f
#define ZL_INV   4.8828125e-4f

__global__ void __launch_bounds__(128)
quantize_tc_kernel(const float* __restrict__ Zp, const float* __restrict__ Zn,
                   const float* __restrict__ cb,
                   float* __restrict__ zq_out,
                   float* __restrict__ loss_part)
{
  __shared__ __align__(16) __half s_hi[128*RPAD];   // z-hi, then candidate tiles
  __shared__ __align__(16) __half s_lo[128*RPAD];   // z-lo(scaled) staging only
  __shared__ float sCC[128];
  __shared__ int2  sTOP[128];

  const int tid = threadIdx.x;
  const int wid = tid >> 5;
  const int lane = tid & 31;
  const int g   = lane >> 2;
  const int tig = lane & 3;
  const int bx  = blockIdx.x;

  const bool isP = (bx < 1024);
  const int local = isP ? bx : bx - 1024;
  const int grp = local >> 1, h = local & 1;
  int l, kp, b;
  if (isP){ l = grp & 3; kp = (grp >> 2) & 7; b = grp >> 5; }
  else    { l = 0;       kp = grp & 31;       b = grp >> 5; }
  const int gidx = isP ? (l*8 + kp) : kp;
  const float* Z = isP ? Zp : Zn;
  __nv_bfloat16* zqh = isP ? g_zqhi[0] : g_zqhi[1];
  __nv_bfloat16* zql = isP ? g_zqlo[0] : g_zqlo[1];
  const int p = h*128 + tid;
  const int col = b*256 + p;

  // ---- load my vector (exact fp32) + zz chain ----
  float z[32];
  float zz = 0.f;
  #pragma unroll
  for (int e=0;e<32;e++){
    float v = Z[((b*1024 + e*32 + gidx)*HW) + p];
    z[e] = v; zz = fmaf(v, v, zz);
  }

  // ---- stage fp16 zh / zl*2048 into smem (row = my vector) ----
  {
    uint32_t hiw[16], low[16];
    #pragma unroll
    for (int i=0;i<16;i++){
      float v0 = z[2*i], v1 = z[2*i+1];
      __half h0 = __float2half_rn(v0);
      __half h1 = __float2half_rn(v1);
      __half l0 = __float2half_rn((v0 - __half2float(h0)) * ZL_SCALE);
      __half l1 = __float2half_rn((v1 - __half2float(h1)) * ZL_SCALE);
      hiw[i] = ((uint32_t)__half_as_ushort(h1) << 16) | (uint32_t)__half_as_ushort(h0);
      low[i] = ((uint32_t)__half_as_ushort(l1) << 16) | (uint32_t)__half_as_ushort(l0);
    }
    uint4* dH = reinterpret_cast<uint4*>(s_hi + tid*RPAD);
    uint4* dL = reinterpret_cast<uint4*>(s_lo + tid*RPAD);
    const uint4* sH = reinterpret_cast<const uint4*>(hiw);
    const uint4* sL = reinterpret_cast<const uint4*>(low);
    #pragma unroll
    for (int i=0;i<4;i++){ dH[i] = sH[i]; dL[i] = sL[i]; }
  }
  __syncthreads();

  // ---- loop-invariant A fragments (2 m-tiles x 2 k-steps, zh + zl_s) ----
  uint32_t aH[2][2][4], aL[2][2][4];
  #pragma unroll
  for (int m=0;m<2;m++){
    #pragma unroll
    for (int s=0;s<2;s++){
      int r0 = wid*32 + m*16 + g;
      int k0 = s*16 + tig*2;
      aH[m][s][0] = *reinterpret_cast<const uint32_t*>(s_hi + r0*RPAD + k0);
      aH[m][s][1] = *reinterpret_cast<const uint32_t*>(s_hi + (r0+8)*RPAD + k0);
      aH[m][s][2] = *reinterpret_cast<const uint32_t*>(s_hi + r0*RPAD + k0 + 8);
      aH[m][s][3] = *reinterpret_cast<const uint32_t*>(s_hi + (r0+8)*RPAD + k0 + 8);
      aL[m][s][0] = *reinterpret_cast<const uint32_t*>(s_lo + r0*RPAD + k0);
      aL[m][s][1] = *reinterpret_cast<const uint32_t*>(s_lo + (r0+8)*RPAD + k0);
      aL[m][s][2] = *reinterpret_cast<const uint32_t*>(s_lo + r0*RPAD + k0 + 8);
      aL[m][s][3] = *reinterpret_cast<const uint32_t*>(s_lo + (r0+8)*RPAD + k0 + 8);
    }
  }
  __syncthreads();

  const uint32_t sHiB = smem_to_u32(s_hi);
  const uint32_t laneB = (((uint32_t)(lane&7))*RPAD + (uint32_t)(lane>>3)*8)*2;

  float tb1[4], tb2[4];
  int   tj1[4], tj2[4];
  #pragma unroll
  for (int i=0;i<4;i++){ tb1[i]=3.4e38f; tb2[i]=3.4e38f; tj1[i]=0; tj2[i]=0; }

  for (int t=0; t<8; t++){
    const int base_n = t*128;
    // candidate tile: 32 fp16 per row (64B) into s_hi only
    {
      const uint4* srcH = reinterpret_cast<const uint4*>(g_cb_h + (base_n + tid)*32);
      uint4* dH = reinterpret_cast<uint4*>(s_hi + tid*RPAD);
      #pragma unroll
      for (int i=0;i<4;i++){ dH[i] = srcH[i]; }
      sCC[tid] = g_cnorm[base_n + tid];
    }
    __syncthreads();

    #pragma unroll 4
    for (int sub=0; sub<16; sub++){
      uint32_t bh0,bh1,bh2,bh3;
      uint32_t off = (uint32_t)sub*(8*RPAD*2) + laneB;
      LDSM_X4(bh0,bh1,bh2,bh3, sHiB + off);

      const int j0 = base_n + sub*8 + tig*2;
      const float cc0 = sCC[sub*8 + tig*2];
      const float cc1 = sCC[sub*8 + tig*2 + 1];

      #pragma unroll
      for (int m=0;m<2;m++){
        float dh0=0.f, dh1=0.f, dh2=0.f, dh3=0.f;
        float dl0=0.f, dl1=0.f, dl2=0.f, dl3=0.f;
        MMA16816H(dh0,dh1,dh2,dh3, aH[m][0][0],aH[m][0][1],aH[m][0][2],aH[m][0][3], bh0,bh1);
        MMA16816H(dl0,dl1,dl2,dl3, aL[m][0][0],aL[m][0][1],aL[m][0][2],aL[m][0][3], bh0,bh1);
        MMA16816H(dh0,dh1,dh2,dh3, aH[m][1][0],aH[m][1][1],aH[m][1][2],aH[m][1][3], bh2,bh3);
        MMA16816H(dl0,dl1,dl2,dl3, aL[m][1][0],aL[m][1][1],aL[m][1][2],aL[m][1][3], bh2,bh3);
        float d0 = fmaf(dl0, ZL_INV, dh0);
        float d1 = fmaf(dl1, ZL_INV, dh1);
        float d2 = fmaf(dl2, ZL_INV, dh2);
        float d3 = fmaf(dl3, ZL_INV, dh3);
        float s00 = fmaf(-2.f, d0, cc0);
        float s01 = fmaf(-2.f, d1, cc1);
        float s10 = fmaf(-2.f, d2, cc0);
        float s11 = fmaf(-2.f, d3, cc1);
        int ia = m*2, ib = m*2+1;
        if (s00 < tb1[ia]){ tb2[ia]=tb1[ia]; tj2[ia]=tj1[ia]; tb1[ia]=s00; tj1[ia]=j0; }
        else if (s00 < tb2[ia]){ tb2[ia]=s00; tj2[ia]=j0; }
        if (s01 < tb1[ia]){ tb2[ia]=tb1[ia]; tj2[ia]=tj1[ia]; tb1[ia]=s01; tj1[ia]=j0+1; }
        else if (s01 < tb2[ia]){ tb2[ia]=s01; tj2[ia]=j0+1; }
        if (s10 < tb1[ib]){ tb2[ib]=tb1[ib]; tj2[ib]=tj1[ib]; tb1[ib]=s10; tj1[ib]=j0; }
        else if (s10 < tb2[ib]){ tb2[ib]=s10; tj2[ib]=j0; }
        if (s11 < tb1[ib]){ tb2[ib]=tb1[ib]; tj2[ib]=tj1[ib]; tb1[ib]=s11; tj1[ib]=j0+1; }
        else if (s11 < tb2[ib]){ tb2[ib]=s11; tj2[ib]=j0+1; }
      }
    }
    __syncthreads();
  }

  // ---- merge top-2 across the 4 lanes sharing each row ----
  #pragma unroll
  for (int idx=0; idx<4; idx++){
    float b1v = tb1[idx], b2v = tb2[idx];
    int   j1v = tj1[idx], j2v = tj2[idx];
    #pragma unroll
    for (int st=1; st<4; st<<=1){
      float o1 = __shfl_xor_sync(0xffffffffu, b1v, st);
      int  oj1 = __shfl_xor_sync(0xffffffffu, j1v, st);
      float o2 = __shfl_xor_sync(0xffffffffu, b2v, st);
      int  oj2 = __shfl_xor_sync(0xffffffffu, j2v, st);
      if (o1 < b1v){
        if (b1v < o2){ b2v = b1v; j2v = j1v; } else { b2v = o2; j2v = oj2; }
        b1v = o1; j1v = oj1;
      } else if (o1 < b2v){ b2v = o1; j2v = oj1; }
    }
    if (tig == 0){
      int vloc = wid*32 + (idx>>1)*16 + g + (idx&1)*8;
      sTOP[vloc] = make_int2(j1v, j2v);
    }
  }
  __syncthreads();

  // ---- exact rescoring (strict <, ascending index) ----
  int2 t2 = sTOP[tid];
  int jlo = t2.x < t2.y ? t2.x : t2.y;
  int jhi = t2.x < t2.y ? t2.y : t2.x;
  float best; int bestj;
  {
    const float4* C = reinterpret_cast<const float4*>(cb + jlo*32);
    float a = 0.f;
    #pragma unroll
    for (int q=0;q<8;q++){
      float4 c = C[q];
      a = fmaf(z[4*q+0], c.x, a);
      a = fmaf(z[4*q+1], c.y, a);
      a = fmaf(z[4*q+2], c.z, a);
      a = fmaf(z[4*q+3], c.w, a);
    }
    best = (zz - 2.f*a) + g_cnorm[jlo];
    bestj = jlo;
  }
  if (jhi != jlo){
    const float4* C = reinterpret_cast<const float4*>(cb + jhi*32);
    float a = 0.f;
    #pragma unroll
    for (int q=0;q<8;q++){
      float4 c = C[q];
      a = fmaf(z[4*q+0], c.x, a);
      a = fmaf(z[4*q+1], c.y, a);
      a = fmaf(z[4*q+2], c.z, a);
      a = fmaf(z[4*q+3], c.w, a);
    }
    float s = (zz - 2.f*a) + g_cnorm[jhi];
    if (s < best){ best = s; bestj = jhi; }
  }

  // ---- deterministic per-tile loss partial ----
  {
    float s = best;
    #pragma unroll
    for (int o=16;o>0;o>>=1) s += __shfl_down_sync(0xffffffffu, s, o);
    __shared__ float red[4];
    if (lane == 0) red[wid] = s;
    __syncthreads();
    if (tid == 0){
      float tsum = 0.f;
      #pragma unroll
      for (int i=0;i<4;i++) tsum += red[i];
      loss_part[bx] = tsum;
    }
  }

  // ---- scatter winning code: zq hi/lo [c][4096] + fp32 zq_out (p branch) -
  const float4* cbest = reinterpret_cast<const float4*>(cb + bestj*32);
  #pragma unroll
  for (int q=0;q<8;q++){
    float4 v4 = cbest[q];
    float vv[4] = {v4.x, v4.y, v4.z, v4.w};
    #pragma unroll
    for (int r=0;r<4;r++){
      int e = q*4 + r;
      __nv_bfloat16 hh, ll; split_bf16(vv[r], hh, ll);
      zqh[(e*32 + gidx)*4096 + col] = hh;
      zql[(e*32 + gidx)*4096 + col] = ll;
      if (isP)
        zq_out[(((b*32 + e)*2048) + kp*256 + p)*4 + l] = vv[r];
    }
  }
}

// ---------------- tensor GEMM (wout / conv_out; no argmin downstream) -----
// OMODE 1: store silu(silu(acc+b)) hi/lo [c][4096] (conv_out's input).
// OMODE 2: final out [b][256][16][16] fp32.
#define WROW 136
#define XROW 72

template<int OMODE>
__global__ void __launch_bounds__(256)
tgemm_kernel(const __nv_bfloat16* __restrict__ WT_hi0, const __nv_bfloat16* __restrict__ WT_hi1,
             const __nv_bfloat16* __restrict__ WT_lo0, const __nv_bfloat16* __restrict__ WT_lo1,
             const float* __restrict__ bias0, const float* __restrict__ bias1,
             const __nv_bfloat16* __restrict__ Xhi0, const __nv_bfloat16* __restrict__ Xhi1,
             const __nv_bfloat16* __restrict__ Xlo0, const __nv_bfloat16* __restrict__ Xlo1,
             float* __restrict__ Yf,
             __nv_bfloat16* __restrict__ Yhi, __nv_bfloat16* __restrict__ Ylo,
             int Kd, int M, int oc_off0, int oc_off1)
{
  const int br = blockIdx.z;
  const __nv_bfloat16* WT_hi = br ? WT_hi1 : WT_hi0;
  const __nv_bfloat16* WT_lo = br ? WT_lo1 : WT_lo0;
  const float* bias = br ? bias1 : bias0;
  const __nv_bfloat16* Xhi = br ? Xhi1 : Xhi0;
  const __nv_bfloat16* Xlo = br ? Xlo1 : Xlo0;
  const int oc_off = br ? oc_off1 : oc_off0;

  __shared__ __align__(16) __nv_bfloat16 sWhi[32*WROW];
  __shared__ __align__(16) __nv_bfloat16 sWlo[32*WROW];
  __shared__ __align__(16) __nv_bfloat16 sXhi[32*XROW];
  __shared__ __align__(16) __nv_bfloat16 sXlo[32*XROW];

  const int tid = threadIdx.x;
  const int warp = tid >> 5, lane = tid & 31;
  const int n0 = blockIdx.x*64, m0 = blockIdx.y*128;
  const int mw = warp*16;
  const int t8 = tid & 7, kk = tid >> 3;

  const uint32_t sWhiB = smem_to_u32(sWhi), sWloB = smem_to_u32(sWlo);
  const uint32_t sXhiB = smem_to_u32(sXhi), sXloB = smem_to_u32(sXlo);
  const uint32_t aRow = (lane&7) + ((lane>>4)&1)*8;
  const uint32_t aCol = mw + ((lane>>3)&1)*8;
  const uint32_t bOffBase = lane*(XROW*2);

  float acc[8][4];
  #pragma unroll
  for (int g=0;g<8;g++)
    #pragma unroll
    for (int i=0;i<4;i++) acc[g][i] = 0.f;

  #pragma unroll 1
  for (int k0=0;k0<Kd;k0+=32){
    {
      const uint4* sh = reinterpret_cast<const uint4*>(WT_hi + (k0+kk)*M + m0 + t8*16);
      const uint4* sl = reinterpret_cast<const uint4*>(WT_lo + (k0+kk)*M + m0 + t8*16);
      uint4* dh = reinterpret_cast<uint4*>(sWhi + kk*WROW + t8*16);
      uint4* dl = reinterpret_cast<uint4*>(sWlo + kk*WROW + t8*16);
      dh[0] = sh[0]; dh[1] = sh[1];
      dl[0] = sl[0]; dl[1] = sl[1];
    }
    {
      *reinterpret_cast<uint4*>(sXhi + kk*XROW + t8*8) =
        *reinterpret_cast<const uint4*>(Xhi + (k0+kk)*4096 + n0 + t8*8);
      *reinterpret_cast<uint4*>(sXlo + kk*XROW + t8*8) =
        *reinterpret_cast<const uint4*>(Xlo + (k0+kk)*4096 + n0 + t8*8);
    }
    __syncthreads();

    uint32_t aH[2][4], aL[2][4];
    #pragma unroll
    for (int s=0;s<2;s++){
      uint32_t off = ((s*16 + aRow)*WROW + aCol)*2;
      LDSM_X4_T(aH[s][0],aH[s][1],aH[s][2],aH[s][3], sWhiB + off);
      LDSM_X4_T(aL[s][0],aL[s][1],aL[s][2],aL[s][3], sWloB + off);
    }
    #pragma unroll
    for (int g=0;g<8;g++){
      uint32_t bh0,bh1,bh2,bh3, bl0,bl1,bl2,bl3;
      LDSM_X4_T(bh0,bh1,bh2,bh3, sXhiB + bOffBase + g*16);
      LDSM_X4_T(bl0,bl1,bl2,bl3, sXloB + bOffBase + g*16);
      MMA16816(acc[g][0],acc[g][1],acc[g][2],acc[g][3], aH[0][0],aH[0][1],aH[0][2],aH[0][3], bh0,bh1);
      MMA16816(acc[g][0],acc[g][1],acc[g][2],acc[g][3], aH[1][0],aH[1][1],aH[1][2],aH[1][3], bh2,bh3);
      MMA16816(acc[g][0],acc[g][1],acc[g][2],acc[g][3], aL[0][0],aL[0][1],aL[0][2],aL[0][3], bh0,bh1);
      MMA16816(acc[g][0],acc[g][1],acc[g][2],acc[g][3], aL[1][0],aL[1][1],aL[1][2],aL[1][3], bh2,bh3);
      MMA16816(acc[g][0],acc[g][1],acc[g][2],acc[g][3], aH[0][0],aH[0][1],aH[0][2],aH[0][3], bl0,bl1);
      MMA16816(acc[g][0],acc[g][1],acc[g][2],acc[g][3], aH[1][0],aH[1][1],aH[1][2],aH[1][3], bl2,bl3);
    }
    __syncthreads();
  }

  const int r0 = m0 + mw + (lane>>2);
  const int r1 = r0 + 8;
  const float bb0 = bias[r0], bb1 = bias[r1];
  #pragma unroll
  for (int g=0;g<8;g++){
    int j = n0 + g*8 + (lane&3)*2;
    float v00 = acc[g][0] + bb0, v01 = acc[g][1] + bb0;
    float v10 = acc[g][2] + bb1, v11 = acc[g][3] + bb1;
    if (OMODE == 1){
      // hout = silu(acc+b); conv_out input = silu(hout): apply silu TWICE.
      float w00 = silu_f(silu_f(v00)), w01 = silu_f(silu_f(v01));
      float w10 = silu_f(silu_f(v10)), w11 = silu_f(silu_f(v11));
      __nv_bfloat16 h0,l0,h1,l1;
      split_bf16(w00,h0,l0); split_bf16(w01,h1,l1);
      uint32_t ph = ((uint32_t)__bfloat16_as_ushort(h1)<<16) | __bfloat16_as_ushort(h0);
      uint32_t pl = ((uint32_t)__bfloat16_as_ushort(l1)<<16) | __bfloat16_as_ushort(l0);
      *reinterpret_cast<uint32_t*>(&Yhi[(oc_off + r0)*4096 + j]) = ph;
      *reinterpret_cast<uint32_t*>(&Ylo[(oc_off + r0)*4096 + j]) = pl;
      split_bf16(w10,h0,l0); split_bf16(w11,h1,l1);
      ph = ((uint32_t)__bfloat16_as_ushort(h1)<<16) | __bfloat16_as_ushort(h0);
      pl = ((uint32_t)__bfloat16_as_ushort(l1)<<16) | __bfloat16_as_ushort(l0);
      *reinterpret_cast<uint32_t*>(&Yhi[(oc_off + r1)*4096 + j]) = ph;
      *reinterpret_cast<uint32_t*>(&Ylo[(oc_off + r1)*4096 + j]) = pl;
    } else {
      int bb = j >> 8, pp = j & 255;
      *reinterpret_cast<float2*>(&Yf[bb*65536 + r0*256 + pp]) = make_float2(v00, v01);
      *reinterpret_cast<float2*>(&Yf[bb*65536 + r1*256 + pp]) = make_float2(v10, v11);
    }
  }
}

// ---------------- deterministic loss finalize ----------------
__global__ void loss_final_kernel(float* __restrict__ out_loss){
  __shared__ float red[256];
  float s = 0.f;
  for (int i=threadIdx.x; i<2048; i+=256) s += g_loss_part[i];
  red[threadIdx.x] = s;
  __syncthreads();
  for (int o=128;o>0;o>>=1){
    if (threadIdx.x < o) red[threadIdx.x] += red[threadIdx.x + o];
    __syncthreads();
  }
  if (threadIdx.x == 0)
    *out_loss = 1.25f * red[0] / 4194304.f;
}

// ---------------- launch ----------------
extern "C" void kernel_launch(void* const* d_in, const int* in_sizes, int n_in,
                              void* d_out, int out_size)
{
  const float* x          = (const float*)d_in[0];
  const float* conv_in_w  = (const float*)d_in[1];
  const float* conv_in_b  = (const float*)d_in[2];
  const float* ln_p_w     = (const float*)d_in[3];
  const float* ln_p_b     = (const float*)d_in[4];
  const float* wp_in      = (const float*)d_in[5];
  const float* bp_in      = (const float*)d_in[6];
  const float* wp_out     = (const float*)d_in[7];
  const float* bp_out     = (const float*)d_in[8];
  const float* ln_n_w     = (const float*)d_in[9];
  const float* ln_n_b     = (const float*)d_in[10];
  const float* wn_in      = (const float*)d_in[11];
  const float* bn_in      = (const float*)d_in[12];
  const float* wn_out     = (const float*)d_in[13];
  const float* bn_out     = (const float*)d_in[14];
  const float* codebook   = (const float*)d_in[15];
  const float* conv_out_w = (const float*)d_in[16];
  const float* conv_out_b = (const float*)d_in[17];

  float* out      = (float*)d_out;               // [16,256,16,16]
  float* out_loss = out + 1048576;               // scalar
  float* out_zq   = out + 1048577;               // [16,32,2048,4]

  float *hbuf, *lnbuf, *zbuf, *lpart;
  __nv_bfloat16 *wTout_hi, *wTout_lo, *wTco_hi, *wTco_lo;
  __nv_bfloat16 *zqhi, *zqlo, *hchi, *hclo;
  cudaGetSymbolAddress((void**)&hbuf,  g_h);
  cudaGetSymbolAddress((void**)&lnbuf, g_ln);
  cudaGetSymbolAddress((void**)&zbuf,  g_z);
  cudaGetSymbolAddress((void**)&lpart, g_loss_part);
  cudaGetSymbolAddress((void**)&wTout_hi, g_wTout_hi);
  cudaGetSymbolAddress((void**)&wTout_lo, g_wTout_lo);
  cudaGetSymbolAddress((void**)&wTco_hi,  g_wTco_hi);
  cudaGetSymbolAddress((void**)&wTco_lo,  g_wTco_lo);
  cudaGetSymbolAddress((void**)&zqhi,  g_zqhi);
  cudaGetSymbolAddress((void**)&zqlo,  g_zqlo);
  cudaGetSymbolAddress((void**)&hchi,  g_hchi);
  cudaGetSymbolAddress((void**)&hclo,  g_hclo);

  float* ln0 = lnbuf;
  float* ln1 = lnbuf + BATCH*128*HW;     // 524288
  float* z0  = zbuf;
  float* z1  = zbuf + BATCH*1024*HW;     // 4194304

  prep_cb_kernel<<<4, 256>>>(codebook);
  prep_w_kernel<<<1280, 256>>>(wp_out, wn_out, conv_out_w);

  // h = conv_in(silu(x)) — scalar fp32 (exact chain)
  gemm_kernel<true,false><<<dim3(64, 2, 1), 256>>>(
      conv_in_w, conv_in_w, conv_in_b, conv_in_b, x, x, hbuf, hbuf,
      256, 256, 256);

  // layernorms -> fp32 [b][128][256] (exact chain)
  ln_stats_kernel<<<dim3(8, BATCH, 2), 256>>>(hbuf);
  ln_apply_kernel<<<dim3(8, BATCH, 2), 256>>>(hbuf, ln_p_w, ln_p_b, ln_n_w, ln_n_b);

  // z = silu(W_in @ ln + b) — scalar fp32 GEMM (exact chain, bit-identical z)
  gemm_kernel<false,true><<<dim3(64, 8, 2), 256>>>(
      wp_in, wn_in, bp_in, bn_in,
      ln0, ln1, z0, z1,
      128, 128, 1024);

  // VQ via fp16 tensor cores + exact rescue (argmin exact)
  quantize_tc_kernel<<<2048, 128>>>(z0, z1, codebook, out_zq, lpart);

  // hout chain: silu(silu(W_out @ zq + b)) hi/lo [c][4096] — tensor (tolerant)
  tgemm_kernel<1><<<dim3(64, 1, 2), 256>>>(
      wTout_hi, wTout_hi + 131072, wTout_lo, wTout_lo + 131072,
      bp_out, bn_out,
      zqhi, zqhi + 4194304, zqlo, zqlo + 4194304,
      nullptr, hchi, hclo,
      1024, 128, 0, 128);

  // out = conv_out(silu(h_cat)) — tensor (tolerant)
  tgemm_kernel<2><<<dim3(64, 2, 1), 256>>>(
      wTco_hi, wTco_hi, wTco_lo, wTco_lo,
      conv_out_b, conv_out_b,
      hchi, hchi, hclo, hclo,
      out, nullptr, nullptr,
      256, 256, 0, 0);

  loss_final_kernel<<<1, 256>>>(out_loss);
}

// round 17
// speedup vs baseline: 2.6037x; 1.0119x over previous
#include <cuda_runtime.h>
#include <cuda_bf16.h>
#include <cuda_fp16.h>
#include <math.h>
#include <stdint.h>

#define BATCH 16
#define HW 256
#define NT (BATCH*HW)   // 4096 total columns

// ---------------- scratch (no allocations allowed) ----------------
__device__ float g_h[BATCH*256*HW];        // conv_in output [b][256][256]
__device__ float g_lnstat[2][BATCH][4][2]; // per-(branch,sample): 4 p-chunk partials
__device__ float g_ln[2][BATCH*128*HW];    // layernorm out fp32 [b][128][256]
__device__ float g_z[2][BATCH*1024*HW];    // z fp32 [b][1024][256] per branch
__device__ __align__(16) __nv_bfloat16 g_zqhi[2][1024*4096];  // zq [c][4096]
__device__ __align__(16) __nv_bfloat16 g_zqlo[2][1024*4096];
__device__ __align__(16) __nv_bfloat16 g_hchi[256*4096];      // silu(hcat) [c][4096]
__device__ __align__(16) __nv_bfloat16 g_hclo[256*4096];
__device__ __align__(16) __nv_bfloat16 g_wTout_hi[2][1024*128];
__device__ __align__(16) __nv_bfloat16 g_wTout_lo[2][1024*128];
__device__ __align__(16) __nv_bfloat16 g_wTco_hi[256*256];
__device__ __align__(16) __nv_bfloat16 g_wTco_lo[256*256];
__device__ float g_cnorm[1024];
__device__ float g_loss_part[2048];
__device__ __align__(16) __half g_cb_h[1024*32];   // codebook fp16 (hi only)

__device__ __forceinline__ float silu_f(float v){ return v / (1.f + expf(-v)); }
__device__ __forceinline__ void split_bf16(float v, __nv_bfloat16& h, __nv_bfloat16& l){
  h = __float2bfloat16(v);
  l = __float2bfloat16(v - __bfloat162float(h));
}
__device__ __forceinline__ uint32_t smem_to_u32(const void* smem_ptr) {
  uint32_t addr;
  asm("{ .reg .u64 tmp; cvta.to.shared.u64 tmp, %1; cvt.u32.u64 %0, tmp; }"
      : "=r"(addr) : "l"(smem_ptr));
  return addr;
}

#define MMA16816(d0,d1,d2,d3,a0,a1,a2,a3,b0,b1) \
  asm volatile("mma.sync.aligned.m16n8k16.row.col.f32.bf16.bf16.f32 " \
      "{%0,%1,%2,%3}, {%4,%5,%6,%7}, {%8,%9}, {%0,%1,%2,%3};" \
      : "+f"(d0), "+f"(d1), "+f"(d2), "+f"(d3) \
      : "r"(a0), "r"(a1), "r"(a2), "r"(a3), "r"(b0), "r"(b1))
#define MMA16816H(d0,d1,d2,d3,a0,a1,a2,a3,b0,b1) \
  asm volatile("mma.sync.aligned.m16n8k16.row.col.f32.f16.f16.f32 " \
      "{%0,%1,%2,%3}, {%4,%5,%6,%7}, {%8,%9}, {%0,%1,%2,%3};" \
      : "+f"(d0), "+f"(d1), "+f"(d2), "+f"(d3) \
      : "r"(a0), "r"(a1), "r"(a2), "r"(a3), "r"(b0), "r"(b1))
#define LDSM_X4(r0,r1,r2,r3,addr) \
  asm volatile("ldmatrix.sync.aligned.m8n8.x4.shared.b16 {%0,%1,%2,%3}, [%4];" \
      : "=r"(r0),"=r"(r1),"=r"(r2),"=r"(r3) : "r"(addr))
#define LDSM_X4_T(r0,r1,r2,r3,addr) \
  asm volatile("ldmatrix.sync.aligned.m8n8.x4.trans.shared.b16 {%0,%1,%2,%3}, [%4];" \
      : "=r"(r0),"=r"(r1),"=r"(r2),"=r"(r3) : "r"(addr))

// ---------------- prep: weights + codebook in ONE launch ----------------
__global__ void prep_kernel(const float* __restrict__ cb,
                            const float* __restrict__ wpo, const float* __restrict__ wno,
                            const float* __restrict__ wco){
  int i = blockIdx.x*blockDim.x + threadIdx.x;
  __nv_bfloat16 h, l;
  if (i < 131072){                 // wp_out [128][1024] -> [k*128+m]
    int m = i >> 10, k = i & 1023;
    split_bf16(wpo[i], h, l);
    g_wTout_hi[0][k*128+m] = h; g_wTout_lo[0][k*128+m] = l;
  } else if (i < 262144){          // wn_out
    int j = i - 131072;
    int m = j >> 10, k = j & 1023;
    split_bf16(wno[j], h, l);
    g_wTout_hi[1][k*128+m] = h; g_wTout_lo[1][k*128+m] = l;
  } else if (i < 327680){          // conv_out_w [256][256] -> [k*256+m]
    int j = i - 262144;
    int m = j >> 8, k = j & 255;
    split_bf16(wco[j], h, l);
    g_wTco_hi[k*256+m] = h; g_wTco_lo[k*256+m] = l;
  } else if (i < 328704){          // codebook norms (exact chain) + fp16 cb
    int j = i - 327680;
    float s = 0.f;
    #pragma unroll
    for (int e=0;e<32;e++){
      float v = cb[j*32+e];
      s = fmaf(v,v,s);
      g_cb_h[j*32+e] = __float2half_rn(v);
    }
    g_cnorm[j] = s;
  }
}

// ---------------- conv_in: scalar FFMA GEMM + fused ln-stats partials -----
// Each block covers exactly one (branch=blockIdx.y, sample, 64-col chunk)
// tile, so it deterministically reduces silu(out) sums into a fixed slot.
__global__ void __launch_bounds__(256)
convin_kernel(const float* __restrict__ W, const float* __restrict__ bias,
              const float* __restrict__ X, float* __restrict__ Y)
{
  __shared__ __align__(16) float As[32][128];
  __shared__ __align__(16) float Bs[32][64];
  const int tid = threadIdx.x;
  const int tx = tid & 15, ty = tid >> 4;
  const int j0 = blockIdx.x * 64;
  const int m0 = blockIdx.y * 128;
  const int b  = j0 >> 8;
  const int p0 = j0 & 255;

  float acc[8][4];
  #pragma unroll
  for (int i=0;i<8;i++)
    #pragma unroll
    for (int j=0;j<4;j++) acc[i][j] = 0.f;

  for (int k0=0;k0<256;k0+=32){
    #pragma unroll
    for (int i=0;i<16;i++){
      int e = tid + i*256;
      int m = e >> 5, k = e & 31;
      As[k][m] = W[(m0+m)*256 + k0 + k];
    }
    #pragma unroll
    for (int i=0;i<8;i++){
      int e = tid + i*256;
      int k = e >> 6, j = e & 63;
      Bs[k][j] = silu_f(X[((b*256) + k0 + k)*HW + p0 + j]);
    }
    __syncthreads();
    #pragma unroll
    for (int kk=0;kk<32;kk++){
      float4 a0 = *reinterpret_cast<const float4*>(&As[kk][ty*8]);
      float4 a1 = *reinterpret_cast<const float4*>(&As[kk][ty*8+4]);
      float4 bv = *reinterpret_cast<const float4*>(&Bs[kk][tx*4]);
      float av[8] = {a0.x,a0.y,a0.z,a0.w,a1.x,a1.y,a1.z,a1.w};
      float bb[4] = {bv.x,bv.y,bv.z,bv.w};
      #pragma unroll
      for (int i=0;i<8;i++)
        #pragma unroll
        for (int j=0;j<4;j++)
          acc[i][j] = fmaf(av[i], bb[j], acc[i][j]);
    }
    __syncthreads();
  }

  float s = 0.f, sq = 0.f;
  #pragma unroll
  for (int i=0;i<8;i++){
    int m = m0 + ty*8 + i;
    float bb = bias[m];
    float4 o;
    o.x = acc[i][0] + bb; o.y = acc[i][1] + bb;
    o.z = acc[i][2] + bb; o.w = acc[i][3] + bb;
    *reinterpret_cast<float4*>(&Y[((b*256) + m)*HW + p0 + tx*4]) = o;
    float v0 = silu_f(o.x), v1 = silu_f(o.y), v2 = silu_f(o.z), v3 = silu_f(o.w);
    s += v0; sq = fmaf(v0, v0, sq);
    s += v1; sq = fmaf(v1, v1, sq);
    s += v2; sq = fmaf(v2, v2, sq);
    s += v3; sq = fmaf(v3, v3, sq);
  }

  // deterministic block reduction -> g_lnstat[br][b][chunk]
  __shared__ float rs[8], rq[8];
  #pragma unroll
  for (int o=16;o>0;o>>=1){
    s  += __shfl_down_sync(0xffffffffu, s,  o);
    sq += __shfl_down_sync(0xffffffffu, sq, o);
  }
  int wid = tid >> 5, lid = tid & 31;
  if (lid == 0){ rs[wid] = s; rq[wid] = sq; }
  __syncthreads();
  if (tid == 0){
    float ts = 0.f, tq = 0.f;
    #pragma unroll
    for (int i=0;i<8;i++){ ts += rs[i]; tq += rq[i]; }
    g_lnstat[blockIdx.y][b][blockIdx.x & 3][0] = ts;
    g_lnstat[blockIdx.y][b][blockIdx.x & 3][1] = tq;
  }
}

// ---------------- scalar FFMA GEMM (bit-exact; wp_in/wn_in) -----
// BM=128 BN=64 BK=32; per-output accumulation strictly sequential in k.
template<bool SILU_IN, bool SILU_OUT>
__global__ void __launch_bounds__(256)
gemm_kernel(const float* __restrict__ W0, const float* __restrict__ W1,
            const float* __restrict__ bias0, const float* __restrict__ bias1,
            const float* __restrict__ X0, const float* __restrict__ X1,
            float* __restrict__ Y0, float* __restrict__ Y1,
            int Kd, int CinTot, int OCtot)
{
  const float* W    = blockIdx.z ? W1 : W0;
  const float* bias = blockIdx.z ? bias1 : bias0;
  const float* X    = blockIdx.z ? X1 : X0;
  float*       Y    = blockIdx.z ? Y1 : Y0;

  __shared__ __align__(16) float As[32][128];
  __shared__ __align__(16) float Bs[32][64];
  const int tid = threadIdx.x;
  const int tx = tid & 15, ty = tid >> 4;
  const int j0 = blockIdx.x * 64;
  const int m0 = blockIdx.y * 128;
  const int b  = j0 >> 8;
  const int p0 = j0 & 255;

  float acc[8][4];
  #pragma unroll
  for (int i=0;i<8;i++)
    #pragma unroll
    for (int j=0;j<4;j++) acc[i][j] = 0.f;

  for (int k0=0;k0<Kd;k0+=32){
    #pragma unroll
    for (int i=0;i<16;i++){
      int e = tid + i*256;
      int m = e >> 5, k = e & 31;
      As[k][m] = W[(m0+m)*Kd + k0 + k];
    }
    #pragma unroll
    for (int i=0;i<8;i++){
      int e = tid + i*256;
      int k = e >> 6, j = e & 63;
      float v = X[((b*CinTot) + k0 + k)*HW + p0 + j];
      if (SILU_IN) v = silu_f(v);
      Bs[k][j] = v;
    }
    __syncthreads();
    #pragma unroll
    for (int kk=0;kk<32;kk++){
      float4 a0 = *reinterpret_cast<const float4*>(&As[kk][ty*8]);
      float4 a1 = *reinterpret_cast<const float4*>(&As[kk][ty*8+4]);
      float4 bv = *reinterpret_cast<const float4*>(&Bs[kk][tx*4]);
      float av[8] = {a0.x,a0.y,a0.z,a0.w,a1.x,a1.y,a1.z,a1.w};
      float bb[4] = {bv.x,bv.y,bv.z,bv.w};
      #pragma unroll
      for (int i=0;i<8;i++)
        #pragma unroll
        for (int j=0;j<4;j++)
          acc[i][j] = fmaf(av[i], bb[j], acc[i][j]);
    }
    __syncthreads();
  }

  #pragma unroll
  for (int i=0;i<8;i++){
    int m = m0 + ty*8 + i;
    float bb = bias[m];
    float4 o;
    o.x = acc[i][0] + bb; o.y = acc[i][1] + bb;
    o.z = acc[i][2] + bb; o.w = acc[i][3] + bb;
    if (SILU_OUT){
      o.x = silu_f(o.x); o.y = silu_f(o.y); o.z = silu_f(o.z); o.w = silu_f(o.w);
    }
    *reinterpret_cast<float4*>(&Y[((b*OCtot) + m)*HW + p0 + tx*4]) = o;
  }
}

// ---------------- layernorm apply (stats pre-reduced by conv_in) ----------
__global__ void ln_apply_kernel(const float* __restrict__ H,
                                const float* __restrict__ wp, const float* __restrict__ bp,
                                const float* __restrict__ wn, const float* __restrict__ bn)
{
  const int c  = blockIdx.x;
  const int b  = blockIdx.y;
  const int br = blockIdx.z;
  float s = 0.f, sq = 0.f;
  #pragma unroll
  for (int i=0;i<4;i++){ s += g_lnstat[br][b][i][0]; sq += g_lnstat[br][b][i][1]; }
  float mu   = s * (1.f/32768.f);
  float var  = sq * (1.f/32768.f) - mu*mu;
  float rstd = rsqrtf(var + 1e-5f);
  const float* base = H + (b*256 + br*128)*HW + c*4096;
  const float* w  = (br ? wn : wp) + c*4096;
  const float* bb = (br ? bn : bp) + c*4096;
  float* ob = g_ln[br] + b*32768 + c*4096;
  for (int i=threadIdx.x; i<4096; i+=256){
    float v = silu_f(base[i]);
    ob[i] = (v - mu) * rstd * w[i] + bb[i];
  }
}

// ---------------- tensor-core VQ (fp16 2-term + exact rescue) -------------
// zc_approx = zh*ch + (zl*2048)*ch * 2^-11 ; score error ~6e-8; exact fp32
// rescoring of approx top-2 gives the exact argmin (strict <, ascending).
#define RPAD 40
#define ZL_SCALE 2048.0f
#define ZL_INV   4.8828125e-4f

__global__ void __launch_bounds__(128)
quantize_tc_kernel(const float* __restrict__ Zp, const float* __restrict__ Zn,
                   const float* __restrict__ cb,
                   float* __restrict__ zq_out,
                   float* __restrict__ loss_part)
{
  __shared__ __align__(16) __half s_hi[128*RPAD];
  __shared__ __align__(16) __half s_lo[128*RPAD];
  __shared__ float sCC[128];
  __shared__ int2  sTOP[128];

  const int tid = threadIdx.x;
  const int wid = tid >> 5;
  const int lane = tid & 31;
  const int g   = lane >> 2;
  const int tig = lane & 3;
  const int bx  = blockIdx.x;

  const bool isP = (bx < 1024);
  const int local = isP ? bx : bx - 1024;
  const int grp = local >> 1, h = local & 1;
  int l, kp, b;
  if (isP){ l = grp & 3; kp = (grp >> 2) & 7; b = grp >> 5; }
  else    { l = 0;       kp = grp & 31;       b = grp >> 5; }
  const int gidx = isP ? (l*8 + kp) : kp;
  const float* Z = isP ? Zp : Zn;
  __nv_bfloat16* zqh = isP ? g_zqhi[0] : g_zqhi[1];
  __nv_bfloat16* zql = isP ? g_zqlo[0] : g_zqlo[1];
  const int p = h*128 + tid;
  const int col = b*256 + p;

  float z[32];
  float zz = 0.f;
  #pragma unroll
  for (int e=0;e<32;e++){
    float v = Z[((b*1024 + e*32 + gidx)*HW) + p];
    z[e] = v; zz = fmaf(v, v, zz);
  }

  {
    uint32_t hiw[16], low[16];
    #pragma unroll
    for (int i=0;i<16;i++){
      float v0 = z[2*i], v1 = z[2*i+1];
      __half h0 = __float2half_rn(v0);
      __half h1 = __float2half_rn(v1);
      __half l0 = __float2half_rn((v0 - __half2float(h0)) * ZL_SCALE);
      __half l1 = __float2half_rn((v1 - __half2float(h1)) * ZL_SCALE);
      hiw[i] = ((uint32_t)__half_as_ushort(h1) << 16) | (uint32_t)__half_as_ushort(h0);
      low[i] = ((uint32_t)__half_as_ushort(l1) << 16) | (uint32_t)__half_as_ushort(l0);
    }
    uint4* dH = reinterpret_cast<uint4*>(s_hi + tid*RPAD);
    uint4* dL = reinterpret_cast<uint4*>(s_lo + tid*RPAD);
    const uint4* sH = reinterpret_cast<const uint4*>(hiw);
    const uint4* sL = reinterpret_cast<const uint4*>(low);
    #pragma unroll
    for (int i=0;i<4;i++){ dH[i] = sH[i]; dL[i] = sL[i]; }
  }
  __syncthreads();

  uint32_t aH[2][2][4], aL[2][2][4];
  #pragma unroll
  for (int m=0;m<2;m++){
    #pragma unroll
    for (int s=0;s<2;s++){
      int r0 = wid*32 + m*16 + g;
      int k0 = s*16 + tig*2;
      aH[m][s][0] = *reinterpret_cast<const uint32_t*>(s_hi + r0*RPAD + k0);
      aH[m][s][1] = *reinterpret_cast<const uint32_t*>(s_hi + (r0+8)*RPAD + k0);
      aH[m][s][2] = *reinterpret_cast<const uint32_t*>(s_hi + r0*RPAD + k0 + 8);
      aH[m][s][3] = *reinterpret_cast<const uint32_t*>(s_hi + (r0+8)*RPAD + k0 + 8);
      aL[m][s][0] = *reinterpret_cast<const uint32_t*>(s_lo + r0*RPAD + k0);
      aL[m][s][1] = *reinterpret_cast<const uint32_t*>(s_lo + (r0+8)*RPAD + k0);
      aL[m][s][2] = *reinterpret_cast<const uint32_t*>(s_lo + r0*RPAD + k0 + 8);
      aL[m][s][3] = *reinterpret_cast<const uint32_t*>(s_lo + (r0+8)*RPAD + k0 + 8);
    }
  }
  __syncthreads();

  const uint32_t sHiB = smem_to_u32(s_hi);
  const uint32_t laneB = (((uint32_t)(lane&7))*RPAD + (uint32_t)(lane>>3)*8)*2;

  float tb1[4], tb2[4];
  int   tj1[4], tj2[4];
  #pragma unroll
  for (int i=0;i<4;i++){ tb1[i]=3.4e38f; tb2[i]=3.4e38f; tj1[i]=0; tj2[i]=0; }

  for (int t=0; t<8; t++){
    const int base_n = t*128;
    {
      const uint4* srcH = reinterpret_cast<const uint4*>(g_cb_h + (base_n + tid)*32);
      uint4* dH = reinterpret_cast<uint4*>(s_hi + tid*RPAD);
      #pragma unroll
      for (int i=0;i<4;i++){ dH[i] = srcH[i]; }
      sCC[tid] = g_cnorm[base_n + tid];
    }
    __syncthreads();

    #pragma unroll 4
    for (int sub=0; sub<16; sub++){
      uint32_t bh0,bh1,bh2,bh3;
      uint32_t off = (uint32_t)sub*(8*RPAD*2) + laneB;
      LDSM_X4(bh0,bh1,bh2,bh3, sHiB + off);

      const int j0 = base_n + sub*8 + tig*2;
      const float cc0 = sCC[sub*8 + tig*2];
      const float cc1 = sCC[sub*8 + tig*2 + 1];

      #pragma unroll
      for (int m=0;m<2;m++){
        float dh0=0.f, dh1=0.f, dh2=0.f, dh3=0.f;
        float dl0=0.f, dl1=0.f, dl2=0.f, dl3=0.f;
        MMA16816H(dh0,dh1,dh2,dh3, aH[m][0][0],aH[m][0][1],aH[m][0][2],aH[m][0][3], bh0,bh1);
        MMA16816H(dl0,dl1,dl2,dl3, aL[m][0][0],aL[m][0][1],aL[m][0][2],aL[m][0][3], bh0,bh1);
        MMA16816H(dh0,dh1,dh2,dh3, aH[m][1][0],aH[m][1][1],aH[m][1][2],aH[m][1][3], bh2,bh3);
        MMA16816H(dl0,dl1,dl2,dl3, aL[m][1][0],aL[m][1][1],aL[m][1][2],aL[m][1][3], bh2,bh3);
        float d0 = fmaf(dl0, ZL_INV, dh0);
        float d1 = fmaf(dl1, ZL_INV, dh1);
        float d2 = fmaf(dl2, ZL_INV, dh2);
        float d3 = fmaf(dl3, ZL_INV, dh3);
        float s00 = fmaf(-2.f, d0, cc0);
        float s01 = fmaf(-2.f, d1, cc1);
        float s10 = fmaf(-2.f, d2, cc0);
        float s11 = fmaf(-2.f, d3, cc1);
        int ia = m*2, ib = m*2+1;
        if (s00 < tb1[ia]){ tb2[ia]=tb1[ia]; tj2[ia]=tj1[ia]; tb1[ia]=s00; tj1[ia]=j0; }
        else if (s00 < tb2[ia]){ tb2[ia]=s00; tj2[ia]=j0; }
        if (s01 < tb1[ia]){ tb2[ia]=tb1[ia]; tj2[ia]=tj1[ia]; tb1[ia]=s01; tj1[ia]=j0+1; }
        else if (s01 < tb2[ia]){ tb2[ia]=s01; tj2[ia]=j0+1; }
        if (s10 < tb1[ib]){ tb2[ib]=tb1[ib]; tj2[ib]=tj1[ib]; tb1[ib]=s10; tj1[ib]=j0; }
        else if (s10 < tb2[ib]){ tb2[ib]=s10; tj2[ib]=j0; }
        if (s11 < tb1[ib]){ tb2[ib]=tb1[ib]; tj2[ib]=tj1[ib]; tb1[ib]=s11; tj1[ib]=j0+1; }
        else if (s11 < tb2[ib]){ tb2[ib]=s11; tj2[ib]=j0+1; }
      }
    }
    __syncthreads();
  }

  #pragma unroll
  for (int idx=0; idx<4; idx++){
    float b1v = tb1[idx], b2v = tb2[idx];
    int   j1v = tj1[idx], j2v = tj2[idx];
    #pragma unroll
    for (int st=1; st<4; st<<=1){
      float o1 = __shfl_xor_sync(0xffffffffu, b1v, st);
      int  oj1 = __shfl_xor_sync(0xffffffffu, j1v, st);
      float o2 = __shfl_xor_sync(0xffffffffu, b2v, st);
      int  oj2 = __shfl_xor_sync(0xffffffffu, j2v, st);
      if (o1 < b1v){
        if (b1v < o2){ b2v = b1v; j2v = j1v; } else { b2v = o2; j2v = oj2; }
        b1v = o1; j1v = oj1;
      } else if (o1 < b2v){ b2v = o1; j2v = oj1; }
    }
    if (tig == 0){
      int vloc = wid*32 + (idx>>1)*16 + g + (idx&1)*8;
      sTOP[vloc] = make_int2(j1v, j2v);
    }
  }
  __syncthreads();

  int2 t2 = sTOP[tid];
  int jlo = t2.x < t2.y ? t2.x : t2.y;
  int jhi = t2.x < t2.y ? t2.y : t2.x;
  float best; int bestj;
  {
    const float4* C = reinterpret_cast<const float4*>(cb + jlo*32);
    float a = 0.f;
    #pragma unroll
    for (int q=0;q<8;q++){
      float4 c = C[q];
      a = fmaf(z[4*q+0], c.x, a);
      a = fmaf(z[4*q+1], c.y, a);
      a = fmaf(z[4*q+2], c.z, a);
      a = fmaf(z[4*q+3], c.w, a);
    }
    best = (zz - 2.f*a) + g_cnorm[jlo];
    bestj = jlo;
  }
  if (jhi != jlo){
    const float4* C = reinterpret_cast<const float4*>(cb + jhi*32);
    float a = 0.f;
    #pragma unroll
    for (int q=0;q<8;q++){
      float4 c = C[q];
      a = fmaf(z[4*q+0], c.x, a);
      a = fmaf(z[4*q+1], c.y, a);
      a = fmaf(z[4*q+2], c.z, a);
      a = fmaf(z[4*q+3], c.w, a);
    }
    float s = (zz - 2.f*a) + g_cnorm[jhi];
    if (s < best){ best = s; bestj = jhi; }
  }

  {
    float s = best;
    #pragma unroll
    for (int o=16;o>0;o>>=1) s += __shfl_down_sync(0xffffffffu, s, o);
    __shared__ float red[4];
    if (lane == 0) red[wid] = s;
    __syncthreads();
    if (tid == 0){
      float tsum = 0.f;
      #pragma unroll
      for (int i=0;i<4;i++) tsum += red[i];
      loss_part[bx] = tsum;
    }
  }

  const float4* cbest = reinterpret_cast<const float4*>(cb + bestj*32);
  #pragma unroll
  for (int q=0;q<8;q++){
    float4 v4 = cbest[q];
    float vv[4] = {v4.x, v4.y, v4.z, v4.w};
    #pragma unroll
    for (int r=0;r<4;r++){
      int e = q*4 + r;
      __nv_bfloat16 hh, ll; split_bf16(vv[r], hh, ll);
      zqh[(e*32 + gidx)*4096 + col] = hh;
      zql[(e*32 + gidx)*4096 + col] = ll;
      if (isP)
        zq_out[(((b*32 + e)*2048) + kp*256 + p)*4 + l] = vv[r];
    }
  }
}

// ---------------- tensor GEMM (wout / conv_out; no argmin downstream) -----
#define WROW 136
#define XROW 72

template<int OMODE>
__global__ void __launch_bounds__(256)
tgemm_kernel(const __nv_bfloat16* __restrict__ WT_hi0, const __nv_bfloat16* __restrict__ WT_hi1,
             const __nv_bfloat16* __restrict__ WT_lo0, const __nv_bfloat16* __restrict__ WT_lo1,
             const float* __restrict__ bias0, const float* __restrict__ bias1,
             const __nv_bfloat16* __restrict__ Xhi0, const __nv_bfloat16* __restrict__ Xhi1,
             const __nv_bfloat16* __restrict__ Xlo0, const __nv_bfloat16* __restrict__ Xlo1,
             float* __restrict__ Yf,
             __nv_bfloat16* __restrict__ Yhi, __nv_bfloat16* __restrict__ Ylo,
             int Kd, int M, int oc_off0, int oc_off1)
{
  const int br = blockIdx.z;
  const __nv_bfloat16* WT_hi = br ? WT_hi1 : WT_hi0;
  const __nv_bfloat16* WT_lo = br ? WT_lo1 : WT_lo0;
  const float* bias = br ? bias1 : bias0;
  const __nv_bfloat16* Xhi = br ? Xhi1 : Xhi0;
  const __nv_bfloat16* Xlo = br ? Xlo1 : Xlo0;
  const int oc_off = br ? oc_off1 : oc_off0;

  __shared__ __align__(16) __nv_bfloat16 sWhi[32*WROW];
  __shared__ __align__(16) __nv_bfloat16 sWlo[32*WROW];
  __shared__ __align__(16) __nv_bfloat16 sXhi[32*XROW];
  __shared__ __align__(16) __nv_bfloat16 sXlo[32*XROW];

  const int tid = threadIdx.x;
  const int warp = tid >> 5, lane = tid & 31;
  const int n0 = blockIdx.x*64, m0 = blockIdx.y*128;
  const int mw = warp*16;
  const int t8 = tid & 7, kk = tid >> 3;

  const uint32_t sWhiB = smem_to_u32(sWhi), sWloB = smem_to_u32(sWlo);
  const uint32_t sXhiB = smem_to_u32(sXhi), sXloB = smem_to_u32(sXlo);
  const uint32_t aRow = (lane&7) + ((lane>>4)&1)*8;
  const uint32_t aCol = mw + ((lane>>3)&1)*8;
  const uint32_t bOffBase = lane*(XROW*2);

  float acc[8][4];
  #pragma unroll
  for (int g=0;g<8;g++)
    #pragma unroll
    for (int i=0;i<4;i++) acc[g][i] = 0.f;

  #pragma unroll 1
  for (int k0=0;k0<Kd;k0+=32){
    {
      const uint4* sh = reinterpret_cast<const uint4*>(WT_hi + (k0+kk)*M + m0 + t8*16);
      const uint4* sl = reinterpret_cast<const uint4*>(WT_lo + (k0+kk)*M + m0 + t8*16);
      uint4* dh = reinterpret_cast<uint4*>(sWhi + kk*WROW + t8*16);
      uint4* dl = reinterpret_cast<uint4*>(sWlo + kk*WROW + t8*16);
      dh[0] = sh[0]; dh[1] = sh[1];
      dl[0] = sl[0]; dl[1] = sl[1];
    }
    {
      *reinterpret_cast<uint4*>(sXhi + kk*XROW + t8*8) =
        *reinterpret_cast<const uint4*>(Xhi + (k0+kk)*4096 + n0 + t8*8);
      *reinterpret_cast<uint4*>(sXlo + kk*XROW + t8*8) =
        *reinterpret_cast<const uint4*>(Xlo + (k0+kk)*4096 + n0 + t8*8);
    }
    __syncthreads();

    uint32_t aH[2][4], aL[2][4];
    #pragma unroll
    for (int s=0;s<2;s++){
      uint32_t off = ((s*16 + aRow)*WROW + aCol)*2;
      LDSM_X4_T(aH[s][0],aH[s][1],aH[s][2],aH[s][3], sWhiB + off);
      LDSM_X4_T(aL[s][0],aL[s][1],aL[s][2],aL[s][3], sWloB + off);
    }
    #pragma unroll
    for (int g=0;g<8;g++){
      uint32_t bh0,bh1,bh2,bh3, bl0,bl1,bl2,bl3;
      LDSM_X4_T(bh0,bh1,bh2,bh3, sXhiB + bOffBase + g*16);
      LDSM_X4_T(bl0,bl1,bl2,bl3, sXloB + bOffBase + g*16);
      MMA16816(acc[g][0],acc[g][1],acc[g][2],acc[g][3], aH[0][0],aH[0][1],aH[0][2],aH[0][3], bh0,bh1);
      MMA16816(acc[g][0],acc[g][1],acc[g][2],acc[g][3], aH[1][0],aH[1][1],aH[1][2],aH[1][3], bh2,bh3);
      MMA16816(acc[g][0],acc[g][1],acc[g][2],acc[g][3], aL[0][0],aL[0][1],aL[0][2],aL[0][3], bh0,bh1);
      MMA16816(acc[g][0],acc[g][1],acc[g][2],acc[g][3], aL[1][0],aL[1][1],aL[1][2],aL[1][3], bh2,bh3);
      MMA16816(acc[g][0],acc[g][1],acc[g][2],acc[g][3], aH[0][0],aH[0][1],aH[0][2],aH[0][3], bl0,bl1);
      MMA16816(acc[g][0],acc[g][1],acc[g][2],acc[g][3], aH[1][0],aH[1][1],aH[1][2],aH[1][3], bl2,bl3);
    }
    __syncthreads();
  }

  const int r0 = m0 + mw + (lane>>2);
  const int r1 = r0 + 8;
  const float bb0 = bias[r0], bb1 = bias[r1];
  #pragma unroll
  for (int g=0;g<8;g++){
    int j = n0 + g*8 + (lane&3)*2;
    float v00 = acc[g][0] + bb0, v01 = acc[g][1] + bb0;
    float v10 = acc[g][2] + bb1, v11 = acc[g][3] + bb1;
    if (OMODE == 1){
      // hout = silu(acc+b); conv_out input = silu(hout): apply silu TWICE.
      float w00 = silu_f(silu_f(v00)), w01 = silu_f(silu_f(v01));
      float w10 = silu_f(silu_f(v10)), w11 = silu_f(silu_f(v11));
      __nv_bfloat16 h0,l0,h1,l1;
      split_bf16(w00,h0,l0); split_bf16(w01,h1,l1);
      uint32_t ph = ((uint32_t)__bfloat16_as_ushort(h1)<<16) | __bfloat16_as_ushort(h0);
      uint32_t pl = ((uint32_t)__bfloat16_as_ushort(l1)<<16) | __bfloat16_as_ushort(l0);
      *reinterpret_cast<uint32_t*>(&Yhi[(oc_off + r0)*4096 + j]) = ph;
      *reinterpret_cast<uint32_t*>(&Ylo[(oc_off + r0)*4096 + j]) = pl;
      split_bf16(w10,h0,l0); split_bf16(w11,h1,l1);
      ph = ((uint32_t)__bfloat16_as_ushort(h1)<<16) | __bfloat16_as_ushort(h0);
      pl = ((uint32_t)__bfloat16_as_ushort(l1)<<16) | __bfloat16_as_ushort(l0);
      *reinterpret_cast<uint32_t*>(&Yhi[(oc_off + r1)*4096 + j]) = ph;
      *reinterpret_cast<uint32_t*>(&Ylo[(oc_off + r1)*4096 + j]) = pl;
    } else {
      int bb = j >> 8, pp = j & 255;
      *reinterpret_cast<float2*>(&Yf[bb*65536 + r0*256 + pp]) = make_float2(v00, v01);
      *reinterpret_cast<float2*>(&Yf[bb*65536 + r1*256 + pp]) = make_float2(v10, v11);
    }
  }
}

// ---------------- deterministic loss finalize ----------------
__global__ void loss_final_kernel(float* __restrict__ out_loss){
  __shared__ float red[256];
  float s = 0.f;
  for (int i=threadIdx.x; i<2048; i+=256) s += g_loss_part[i];
  red[threadIdx.x] = s;
  __syncthreads();
  for (int o=128;o>0;o>>=1){
    if (threadIdx.x < o) red[threadIdx.x] += red[threadIdx.x + o];
    __syncthreads();
  }
  if (threadIdx.x == 0)
    *out_loss = 1.25f * red[0] / 4194304.f;
}

// ---------------- launch ----------------
extern "C" void kernel_launch(void* const* d_in, const int* in_sizes, int n_in,
                              void* d_out, int out_size)
{
  const float* x          = (const float*)d_in[0];
  const float* conv_in_w  = (const float*)d_in[1];
  const float* conv_in_b  = (const float*)d_in[2];
  const float* ln_p_w     = (const float*)d_in[3];
  const float* ln_p_b     = (const float*)d_in[4];
  const float* wp_in      = (const float*)d_in[5];
  const float* bp_in      = (const float*)d_in[6];
  const float* wp_out     = (const float*)d_in[7];
  const float* bp_out     = (const float*)d_in[8];
  const float* ln_n_w     = (const float*)d_in[9];
  const float* ln_n_b     = (const float*)d_in[10];
  const float* wn_in      = (const float*)d_in[11];
  const float* bn_in      = (const float*)d_in[12];
  const float* wn_out     = (const float*)d_in[13];
  const float* bn_out     = (const float*)d_in[14];
  const float* codebook   = (const float*)d_in[15];
  const float* conv_out_w = (const float*)d_in[16];
  const float* conv_out_b = (const float*)d_in[17];

  float* out      = (float*)d_out;               // [16,256,16,16]
  float* out_loss = out + 1048576;               // scalar
  float* out_zq   = out + 1048577;               // [16,32,2048,4]

  float *hbuf, *lnbuf, *zbuf, *lpart;
  __nv_bfloat16 *wTout_hi, *wTout_lo, *wTco_hi, *wTco_lo;
  __nv_bfloat16 *zqhi, *zqlo, *hchi, *hclo;
  cudaGetSymbolAddress((void**)&hbuf,  g_h);
  cudaGetSymbolAddress((void**)&lnbuf, g_ln);
  cudaGetSymbolAddress((void**)&zbuf,  g_z);
  cudaGetSymbolAddress((void**)&lpart, g_loss_part);
  cudaGetSymbolAddress((void**)&wTout_hi, g_wTout_hi);
  cudaGetSymbolAddress((void**)&wTout_lo, g_wTout_lo);
  cudaGetSymbolAddress((void**)&wTco_hi,  g_wTco_hi);
  cudaGetSymbolAddress((void**)&wTco_lo,  g_wTco_lo);
  cudaGetSymbolAddress((void**)&zqhi,  g_zqhi);
  cudaGetSymbolAddress((void**)&zqlo,  g_zqlo);
  cudaGetSymbolAddress((void**)&hchi,  g_hchi);
  cudaGetSymbolAddress((void**)&hclo,  g_hclo);

  float* ln0 = lnbuf;
  float* ln1 = lnbuf + BATCH*128*HW;     // 524288
  float* z0  = zbuf;
  float* z1  = zbuf + BATCH*1024*HW;     // 4194304

  // prep: weights + codebook in one launch (328704 work items)
  prep_kernel<<<1284, 256>>>(codebook, wp_out, wn_out, conv_out_w);

  // h = conv_in(silu(x)) + fused deterministic ln-stats partials
  convin_kernel<<<dim3(64, 2, 1), 256>>>(conv_in_w, conv_in_b, x, hbuf);

  // layernorm apply -> fp32 [b][128][256] (exact chain)
  ln_apply_kernel<<<dim3(8, BATCH, 2), 256>>>(hbuf, ln_p_w, ln_p_b, ln_n_w, ln_n_b);

  // z = silu(W_in @ ln + b) — scalar fp32 GEMM (exact chain, bit-identical z)
  gemm_kernel<false,true><<<dim3(64, 8, 2), 256>>>(
      wp_in, wn_in, bp_in, bn_in,
      ln0, ln1, z0, z1,
      128, 128, 1024);

  // VQ via fp16 tensor cores + exact rescue (argmin exact)
  quantize_tc_kernel<<<2048, 128>>>(z0, z1, codebook, out_zq, lpart);

  // hout chain: silu(silu(W_out @ zq + b)) hi/lo [c][4096] — tensor (tolerant)
  tgemm_kernel<1><<<dim3(64, 1, 2), 256>>>(
      wTout_hi, wTout_hi + 131072, wTout_lo, wTout_lo + 131072,
      bp_out, bn_out,
      zqhi, zqhi + 4194304, zqlo, zqlo + 4194304,
      nullptr, hchi, hclo,
      1024, 128, 0, 128);

  // out = conv_out(silu(h_cat)) — tensor (tolerant)
  tgemm_kernel<2><<<dim3(64, 2, 1), 256>>>(
      wTco_hi, wTco_hi, wTco_lo, wTco_lo,
      conv_out_b, conv_out_b,
      hchi, hchi, hclo, hclo,
      out, nullptr, nullptr,
      256, 256, 0, 0);

  loss_final_kernel<<<1, 256>>>(out_loss);
}